// round 8
// baseline (speedup 1.0000x reference)
#include <cuda_runtime.h>
#include <cuda_bf16.h>
#include <math.h>
#include <stdint.h>

#define BSZ    32
#define DIMN   384
#define NTOK   577
#define NTOKP  640
#define NPATCH 576
#define PD     768
#define DEPTH  12
#define NCLS   1000
#define EPSC   1e-5f
#define MTOK   (BSZ*NTOK)    // 18464
#define MPAT   (BSZ*NPATCH)  // 18432
#define NQK    768

// ===================== scratch (static device globals; zero-initialized) =====================
__device__ float g_tmp[(size_t)MPAT*DIMN];
__device__ float g_vf [(size_t)MTOK*DIMN];
__device__ float g_s  [(size_t)BSZ*NTOK*NTOK];
__device__ float g_wvstat[DEPTH*2*DIMN];

#define PLANE(name, sz) __device__ __align__(16) __nv_bfloat16 name[(size_t)(sz)]
PLANE(g_xph, (size_t)MPAT*PD);    PLANE(g_xpl, (size_t)MPAT*PD);
PLANE(g_wpth, DIMN*PD);           PLANE(g_wptl, DIMN*PD);
PLANE(g_wqkth, (size_t)DEPTH*NQK*DIMN); PLANE(g_wqktl, (size_t)DEPTH*NQK*DIMN);
PLANE(g_wvth, (size_t)DEPTH*DIMN*DIMN); PLANE(g_wvtl, (size_t)DEPTH*DIMN*DIMN);
PLANE(g_x0h, (size_t)MTOK*DIMN);  PLANE(g_x0l, (size_t)MTOK*DIMN);
PLANE(g_x1h, (size_t)MTOK*DIMN);  PLANE(g_x1l, (size_t)MTOK*DIMN);
PLANE(g_qkh, (size_t)MTOK*NQK);   PLANE(g_qkl, (size_t)MTOK*NQK);
PLANE(g_vth, (size_t)BSZ*DIMN*NTOKP); PLANE(g_vtl, (size_t)BSZ*DIMN*NTOKP);
PLANE(g_ph,  (size_t)BSZ*NTOK*NTOKP); PLANE(g_pl,  (size_t)BSZ*NTOK*NTOKP);

// ===================== small helpers =====================
__device__ __forceinline__ void bsplit(float f, __nv_bfloat16& h, __nv_bfloat16& l) {
    h = __float2bfloat16(f);
    l = __float2bfloat16(f - __bfloat162float(h));
}

__device__ __forceinline__ float block_reduce_sum(float v, float* sbuf) {
    int tid = threadIdx.x;
    sbuf[tid] = v; __syncthreads();
    for (int s = blockDim.x >> 1; s > 0; s >>= 1) {
        if (tid < s) sbuf[tid] += sbuf[tid + s];
        __syncthreads();
    }
    float r = sbuf[0]; __syncthreads();
    return r;
}

__device__ __forceinline__ uint32_t smem_u32(const void* p) {
    uint32_t a;
    asm("{ .reg .u64 t; cvta.to.shared.u64 t, %1; cvt.u32.u64 %0, t; }" : "=r"(a) : "l"(p));
    return a;
}

__device__ __forceinline__ void mma_bf16(float* c, const uint32_t* a, const uint32_t* b) {
    asm volatile(
        "mma.sync.aligned.m16n8k16.row.col.f32.bf16.bf16.f32 "
        "{%0,%1,%2,%3},{%4,%5,%6,%7},{%8,%9},{%0,%1,%2,%3};\n"
        : "+f"(c[0]), "+f"(c[1]), "+f"(c[2]), "+f"(c[3])
        : "r"(a[0]), "r"(a[1]), "r"(a[2]), "r"(a[3]), "r"(b[0]), "r"(b[1]));
}

__device__ __forceinline__ void ldsm4(uint32_t* r, uint32_t addr) {
    asm volatile("ldmatrix.sync.aligned.m8n8.x4.shared.b16 {%0,%1,%2,%3}, [%4];"
                 : "=r"(r[0]), "=r"(r[1]), "=r"(r[2]), "=r"(r[3]) : "r"(addr));
}

__device__ __forceinline__ void cpasync16(uint32_t dst, const void* src, int srcsize) {
    asm volatile("cp.async.cg.shared.global [%0], [%1], 16, %2;"
                 :: "r"(dst), "l"(src), "r"(srcsize) : "memory");
}
#define CP_COMMIT() asm volatile("cp.async.commit_group;" ::: "memory")
template<int NG> __device__ __forceinline__ void cp_wait() {
    asm volatile("cp.async.wait_group %0;" :: "n"(NG) : "memory");
}

// smem stage: 4 planes (Ah, Al, Bh, Bl), each 128 rows x 32 bf16, pitch 40 bf16 (80 B)
#define SPITCH    40
#define PLANE_B   (128 * SPITCH * 2)     // 10240
#define STAGE_B   (4 * PLANE_B)          // 40960
#define SMEM_BYTES (2 * STAGE_B)         // 81920 -> 2 CTAs/SM ; epilogue reuses 128*129*4

#define NTHR 128                         // 4 warps; warp tile 64x64

// ===================== bf16 split-plane tensor GEMM (mma.sync) =====================
// C[M,N] = A[M,K] * B[N,K]^T ; bf16 hi/lo planes, K-major, K mult of 32, rows 16B-aligned.
// EPI: 1 fp32+bias, 2 fp32*alpha, 3 planes (Ph/Pl at ldp),
//      4 out: p = 0.5*(val - C[ix]) + 0.5*(Xh+Xl)[ip] -> planes only,
//      5 v: fp32 C + transposed planes vt[(b*DIMN+gn)*NTOKP + tok]
template<int EPI>
__global__ void __launch_bounds__(NTHR, 2)
tc_gemm(const __nv_bfloat16* __restrict__ Ah, const __nv_bfloat16* __restrict__ Al,
        int lda, long sA,
        const __nv_bfloat16* __restrict__ Bh, const __nv_bfloat16* __restrict__ Bl,
        int ldb, long sB,
        float* __restrict__ C, int ldc, long sC,
        int M, int N, int K, float alpha,
        const float* __restrict__ bias,
        const __nv_bfloat16* __restrict__ Xh, const __nv_bfloat16* __restrict__ Xl, long sX,
        __nv_bfloat16* __restrict__ Ph, __nv_bfloat16* __restrict__ Pl,
        int ldp, long sP)
{
    extern __shared__ char smem[];
    uint32_t sbase = smem_u32(smem);
    int tid = threadIdx.x, lane = tid & 31, wid = tid >> 5;
    int wm = wid >> 1, wn = wid & 1;       // 4 warps: warp tile 64x64 at (wm*64, wn*64)
    int z = blockIdx.z;
    Ah += (size_t)z * sA; Al += (size_t)z * sA;
    Bh += (size_t)z * sB; Bl += (size_t)z * sB;
    if (EPI == 1 || EPI == 2 || EPI == 4 || EPI == 5) C += (size_t)z * sC;
    if (EPI == 4) { Xh += (size_t)z * sX; Xl += (size_t)z * sX; }
    if (EPI == 3 || EPI == 4) { Ph += (size_t)z * sP; Pl += (size_t)z * sP; }
    int m0 = blockIdx.y * 128, n0 = blockIdx.x * 128;

    float acc[4][8][4];                    // [mt m16][nt n8][frag]
    #pragma unroll
    for (int i = 0; i < 4; i++)
        #pragma unroll
        for (int j = 0; j < 8; j++)
            #pragma unroll
            for (int r = 0; r < 4; r++) acc[i][j][r] = 0.f;

    int arow = (lane & 7) + ((lane >> 3) & 1) * 8;
    int acol = (lane >> 4) * 8;
    int brow = (lane & 7) + ((lane >> 4) ? 8 : 0);
    int bcol = ((lane >> 3) & 1) * 8;

    auto stage_load = [&](int t) {
        uint32_t sb = sbase + (uint32_t)(t & 1) * STAGE_B;
        long k0 = (long)t * 32;
        #pragma unroll
        for (int it = 0; it < 4; it++) {
            int e = tid + it * NTHR;                 // 0..511
            int r = e >> 2, c4 = e & 3;
            uint32_t d = sb + (uint32_t)(r * (SPITCH*2) + c4 * 16);
            int gm = m0 + r;
            bool okA = gm < M;
            const char* pAh = (const char*)(Ah + (long)(okA ? gm : 0) * lda + k0) + c4 * 16;
            const char* pAl = (const char*)(Al + (long)(okA ? gm : 0) * lda + k0) + c4 * 16;
            cpasync16(d,             pAh, okA ? 16 : 0);
            cpasync16(d + PLANE_B,   pAl, okA ? 16 : 0);
            int gn = n0 + r;
            bool okB = gn < N;
            const char* pBh = (const char*)(Bh + (long)(okB ? gn : 0) * ldb + k0) + c4 * 16;
            const char* pBl = (const char*)(Bl + (long)(okB ? gn : 0) * ldb + k0) + c4 * 16;
            cpasync16(d + 2*PLANE_B, pBh, okB ? 16 : 0);
            cpasync16(d + 3*PLANE_B, pBl, okB ? 16 : 0);
        }
        CP_COMMIT();
    };

    auto compute = [&](int buf) {
        uint32_t sb = sbase + (uint32_t)buf * STAGE_B;
        uint32_t aAh = sb +             (uint32_t)((wm*64 + arow) * (SPITCH*2) + acol*2);
        uint32_t aAl = aAh + PLANE_B;
        uint32_t aBh = sb + 2*PLANE_B + (uint32_t)((wn*64 + brow) * (SPITCH*2) + bcol*2);
        uint32_t aBl = aBh + PLANE_B;
        #pragma unroll
        for (int s = 0; s < 2; s++) {
            uint32_t koff = (uint32_t)(s * 16 * 2);
            // A fragments: live across both n-halves (the reuse that cuts smem traffic)
            uint32_t ah[4][4], al[4][4];
            #pragma unroll
            for (int mt = 0; mt < 4; mt++) {
                uint32_t ro = (uint32_t)(mt * 16 * (SPITCH*2)) + koff;
                ldsm4(ah[mt], aAh + ro);
                ldsm4(al[mt], aAl + ro);
            }
            #pragma unroll
            for (int half = 0; half < 2; half++) {
                uint32_t bh2[2][4], bl2[2][4];
                #pragma unroll
                for (int np = 0; np < 2; np++) {
                    uint32_t ro = (uint32_t)((half*2 + np) * 16 * (SPITCH*2)) + koff;
                    ldsm4(bh2[np], aBh + ro);
                    ldsm4(bl2[np], aBl + ro);
                }
                // product-major: 16 independent MMAs between same-acc reuse
                #pragma unroll
                for (int mt = 0; mt < 4; mt++)
                    #pragma unroll
                    for (int nt = 0; nt < 4; nt++)
                        mma_bf16(acc[mt][half*4 + nt], ah[mt], &bh2[nt >> 1][(nt & 1) * 2]);
                #pragma unroll
                for (int mt = 0; mt < 4; mt++)
                    #pragma unroll
                    for (int nt = 0; nt < 4; nt++)
                        mma_bf16(acc[mt][half*4 + nt], ah[mt], &bl2[nt >> 1][(nt & 1) * 2]);
                #pragma unroll
                for (int mt = 0; mt < 4; mt++)
                    #pragma unroll
                    for (int nt = 0; nt < 4; nt++)
                        mma_bf16(acc[mt][half*4 + nt], al[mt], &bh2[nt >> 1][(nt & 1) * 2]);
            }
        }
    };

    int nk = K / 32;
    stage_load(0);
    for (int t = 0; t < nk; t++) {
        if (t + 1 < nk) { stage_load(t + 1); cp_wait<1>(); }
        else            { cp_wait<0>(); }
        __syncthreads();
        compute(t & 1);
        __syncthreads();
    }

    // epilogue: regs -> smem (pitch 129 floats; conflict-free rows AND columns)
    float* sst = (float*)smem;
    int g = lane >> 2, tq = lane & 3;
    #pragma unroll
    for (int mt = 0; mt < 4; mt++)
        #pragma unroll
        for (int nt = 0; nt < 8; nt++)
            #pragma unroll
            for (int r = 0; r < 4; r++) {
                int m = wm*64 + mt*16 + g + ((r >= 2) ? 8 : 0);
                int n = wn*64 + nt*8 + 2*tq + (r & 1);
                sst[m * 129 + n] = acc[mt][nt][r];
            }
    __syncthreads();

    if (EPI == 1 || EPI == 2 || EPI == 3 || EPI == 4) {
        for (int e = tid; e < 16384; e += NTHR) {
            int r = e >> 7, c = e & 127;
            int gm = m0 + r, gn = n0 + c;
            if (gm >= M || gn >= N) continue;
            float val = sst[r * 129 + c];
            if (EPI == 1) {
                C[(long)gm * ldc + gn] = val + bias[gn];
            } else if (EPI == 2) {
                C[(long)gm * ldc + gn] = val * alpha;
            } else if (EPI == 3) {
                __nv_bfloat16 h, l; bsplit(val, h, l);
                long ip = (long)gm * ldp + gn;
                Ph[ip] = h; Pl[ip] = l;
            } else {  // EPI 4
                long ix = (long)gm * ldc + gn;
                long ip = (long)gm * ldp + gn;
                float xprev = __bfloat162float(Xh[ip]) + __bfloat162float(Xl[ip]);
                float v2 = 0.5f * (val - C[ix]) + 0.5f * xprev;
                __nv_bfloat16 h, l; bsplit(v2, h, l);
                Ph[ip] = h; Pl[ip] = l;
            }
        }
    } else {  // EPI 5: v — fp32 C plus transposed planes
        for (int e = tid; e < 16384; e += NTHR) {
            int r = e >> 7, c = e & 127;
            int gm = m0 + r, gn = n0 + c;
            if (gm >= M || gn >= N) continue;
            C[(long)gm * ldc + gn] = sst[r * 129 + c];
        }
        for (int e = tid; e < 16384; e += NTHR) {
            int c = e >> 7, r = e & 127;          // consecutive tid -> consecutive r (gm)
            int gm = m0 + r, gn = n0 + c;
            if (gm >= M || gn >= N) continue;
            float val = sst[r * 129 + c];
            int b = gm / NTOK, tok = gm - b * NTOK;
            long it = ((long)b * DIMN + gn) * NTOKP + tok;
            __nv_bfloat16 h, l; bsplit(val, h, l);
            Ph[it] = h; Pl[it] = l;
        }
    }
}

// ===================== elementwise kernels =====================
__global__ void ln1_patchify_kernel(const float* __restrict__ img,
                                    const float* __restrict__ g1,
                                    const float* __restrict__ b1) {
    int p = blockIdx.x, b = blockIdx.y, tid = threadIdx.x;
    int phh = p / 24, pw = p % 24;
    __shared__ float sv[PD];
    __shared__ float sred[256];
    int pr = tid >> 4, pc = tid & 15;
    float s1 = 0.f, s2 = 0.f;
    #pragma unroll
    for (int c = 0; c < 3; c++) {
        float v = img[(((size_t)b*3 + c)*384 + (phh*16 + pr))*384 + (pw*16 + pc)];
        sv[(pr*16 + pc)*3 + c] = v;
        s1 += v; s2 += v*v;
    }
    float tot  = block_reduce_sum(s1, sred);
    float tot2 = block_reduce_sum(s2, sred);
    float mean = tot / PD;
    float var  = tot2 / PD - mean*mean;
    float rs   = rsqrtf(var + EPSC);
    size_t base = ((size_t)b*NPATCH + p)*PD;
    for (int d = tid; d < PD; d += 256) {
        float f = (sv[d] - mean)*rs*g1[d] + b1[d];
        __nv_bfloat16 h, l; bsplit(f, h, l);
        g_xph[base + d] = h; g_xpl[base + d] = l;
    }
}

__global__ void ln2_assemble_kernel(const float* __restrict__ g2,
                                    const float* __restrict__ b2,
                                    const float* __restrict__ pos,
                                    const float* __restrict__ cls) {
    int t = blockIdx.x, b = blockIdx.y, tid = threadIdx.x;
    size_t base = ((size_t)b*NTOK + t)*DIMN;
    if (t == 0) {
        for (int d = tid; d < DIMN; d += 128) {
            float f = cls[d] + pos[d];
            __nv_bfloat16 h, l; bsplit(f, h, l);
            g_x0h[base + d] = h; g_x0l[base + d] = l;
        }
        return;
    }
    __shared__ float sv[DIMN];
    __shared__ float sred[128];
    const float* in = g_tmp + ((size_t)b*NPATCH + (t-1))*DIMN;
    float s1 = 0.f, s2 = 0.f;
    for (int d = tid; d < DIMN; d += 128) { float v = in[d]; sv[d] = v; s1 += v; s2 += v*v; }
    float tot  = block_reduce_sum(s1, sred);
    float tot2 = block_reduce_sum(s2, sred);
    float mean = tot / DIMN;
    float var  = tot2 / DIMN - mean*mean;
    float rs   = rsqrtf(var + EPSC);
    for (int d = tid; d < DIMN; d += 128) {
        float f = (sv[d] - mean)*rs*g2[d] + b2[d] + pos[(size_t)t*DIMN + d];
        __nv_bfloat16 h, l; bsplit(f, h, l);
        g_x0h[base + d] = h; g_x0l[base + d] = l;
    }
}

// per-layer, per-column-k stats of lv (blockIdx.y = layer)
__global__ void wvstat_kernel(const float* __restrict__ wv_raw) {
    int k = blockIdx.x, l = blockIdx.y, tid = threadIdx.x;
    const float* lv = wv_raw + (size_t)l*DIMN*DIMN;
    __shared__ float sred[128];
    float mx = -1e30f;
    for (int a = tid; a < DIMN; a += 128) mx = fmaxf(mx, lv[(size_t)a*DIMN + k]);
    sred[tid] = mx; __syncthreads();
    for (int s = 64; s > 0; s >>= 1) { if (tid < s) sred[tid] = fmaxf(sred[tid], sred[tid+s]); __syncthreads(); }
    mx = sred[0]; __syncthreads();
    float sm = 0.f;
    for (int a = tid; a < DIMN; a += 128) sm += __expf(lv[(size_t)a*DIMN + k] - mx);
    float tot = block_reduce_sum(sm, sred);
    if (tid == 0) {
        g_wvstat[(size_t)l*2*DIMN + k] = mx;
        g_wvstat[(size_t)l*2*DIMN + DIMN + k] = 1.f / (tot * (float)DIMN);
    }
}

__global__ void wvT_kernel(const float* __restrict__ wv_raw) {
    int n = blockIdx.x, l = blockIdx.y, tid = threadIdx.x;
    const float* lv = wv_raw + (size_t)l*DIMN*DIMN;
    const float* st = g_wvstat + (size_t)l*2*DIMN;
    size_t ob = (size_t)l*DIMN*DIMN + (size_t)n*DIMN;
    for (int k = tid; k < DIMN; k += 128) {
        float f = __expf(lv[(size_t)n*DIMN + k] - st[k]) * st[DIMN + k];
        __nv_bfloat16 h, l2; bsplit(f, h, l2);
        g_wvth[ob + k] = h; g_wvtl[ob + k] = l2;
    }
}

// fp32 [R,C] -> bf16 hi/lo planes [C, Rpad] (zero-pad r>=R)
__global__ void transconv_kernel(const float* __restrict__ src, int R, int Cc, int pitch, long sZ,
                                 __nv_bfloat16* __restrict__ dh, __nv_bfloat16* __restrict__ dl,
                                 int Rpad, long dZ) {
    __shared__ float tile[32][33];
    int z = blockIdx.z;
    src += (size_t)z * sZ; dh += (size_t)z * dZ; dl += (size_t)z * dZ;
    int rb = blockIdx.x * 32, cb = blockIdx.y * 32;
    int tx = threadIdx.x, ty = threadIdx.y;   // 32 x 8
    #pragma unroll
    for (int i = 0; i < 4; i++) {
        int r = rb + ty + i*8, c = cb + tx;
        tile[ty + i*8][tx] = (r < R && c < Cc) ? src[(long)r*pitch + c] : 0.f;
    }
    __syncthreads();
    #pragma unroll
    for (int i = 0; i < 4; i++) {
        int dr = cb + ty + i*8;
        int dc = rb + tx;
        if (dr < Cc && dc < Rpad) {
            float f = tile[tx][ty + i*8];
            __nv_bfloat16 h, l; bsplit(f, h, l);
            dh[(long)dr*Rpad + dc] = h; dl[(long)dr*Rpad + dc] = l;
        }
    }
}

// column softmax over axis i -> probs planes [i][NTOKP] (pad cols stay zero-init)
__global__ void colsoftmax_kernel() {
    int j = blockIdx.x * blockDim.x + threadIdx.x;
    int b = blockIdx.y;
    if (j >= NTOK) return;
    const float* s = g_s + (size_t)b*NTOK*NTOK;
    __nv_bfloat16* ph = g_ph + (size_t)b*NTOK*NTOKP;
    __nv_bfloat16* pl = g_pl + (size_t)b*NTOK*NTOKP;
    float m = -1e30f, sum = 0.f;
    for (int i = 0; i < NTOK; i++) {
        float v = s[(size_t)i*NTOK + j];
        float nm = fmaxf(m, v);
        sum = sum * __expf(m - nm) + __expf(v - nm);
        m = nm;
    }
    float inv = 1.f / sum;
    for (int i = 0; i < NTOK; i++) {
        float p = __expf(s[(size_t)i*NTOK + j] - m) * inv;
        __nv_bfloat16 h, l; bsplit(p, h, l);
        ph[(size_t)i*NTOKP + j] = h;
        pl[(size_t)i*NTOKP + j] = l;
    }
}

__global__ void head_kernel(const __nv_bfloat16* __restrict__ xh,
                            const __nv_bfloat16* __restrict__ xl,
                            const float* __restrict__ Wh,
                            const float* __restrict__ bh,
                            float* __restrict__ out) {
    int b = blockIdx.x, tid = threadIdx.x;
    __shared__ float sx[DIMN];
    for (int d = tid; d < DIMN; d += 256) {
        size_t ix = (size_t)b*NTOK*DIMN + d;
        sx[d] = __bfloat162float(xh[ix]) + __bfloat162float(xl[ix]);
    }
    __syncthreads();
    for (int n = tid; n < NCLS; n += 256) {
        float acc = bh[n];
        #pragma unroll 4
        for (int kk = 0; kk < DIMN; kk++)
            acc += sx[kk] * Wh[(size_t)kk*NCLS + n];
        out[(size_t)b*NCLS + n] = acc;
    }
}

// ===================== launch =====================
extern "C" void kernel_launch(void* const* d_in, const int* in_sizes, int n_in,
                              void* d_out, int out_size) {
    const float* img    = (const float*)d_in[0];
    const float* ln1_g  = (const float*)d_in[1];
    const float* ln1_b  = (const float*)d_in[2];
    const float* Wp     = (const float*)d_in[3];
    const float* bp     = (const float*)d_in[4];
    const float* ln2_g  = (const float*)d_in[5];
    const float* ln2_b  = (const float*)d_in[6];
    const float* pos    = (const float*)d_in[7];
    const float* cls    = (const float*)d_in[8];
    const float* wk     = (const float*)d_in[9];
    const float* wq     = (const float*)d_in[10];
    const float* wv_raw = (const float*)d_in[11];
    const float* Wh     = (const float*)d_in[12];
    const float* bh     = (const float*)d_in[13];
    float* out = (float*)d_out;

    cudaFuncSetAttribute(tc_gemm<1>, cudaFuncAttributeMaxDynamicSharedMemorySize, SMEM_BYTES);
    cudaFuncSetAttribute(tc_gemm<2>, cudaFuncAttributeMaxDynamicSharedMemorySize, SMEM_BYTES);
    cudaFuncSetAttribute(tc_gemm<3>, cudaFuncAttributeMaxDynamicSharedMemorySize, SMEM_BYTES);
    cudaFuncSetAttribute(tc_gemm<4>, cudaFuncAttributeMaxDynamicSharedMemorySize, SMEM_BYTES);
    cudaFuncSetAttribute(tc_gemm<5>, cudaFuncAttributeMaxDynamicSharedMemorySize, SMEM_BYTES);

    float *tmp, *vf, *sf;
    cudaGetSymbolAddress((void**)&tmp, g_tmp);
    cudaGetSymbolAddress((void**)&vf,  g_vf);
    cudaGetSymbolAddress((void**)&sf,  g_s);
    __nv_bfloat16 *xph,*xpl,*wpth,*wptl,*wqkth,*wqktl,*wvth,*wvtl;
    __nv_bfloat16 *x0h,*x0l,*x1h,*x1l,*qkh,*qkl,*vth,*vtl,*pph,*ppl;
    cudaGetSymbolAddress((void**)&xph, g_xph);     cudaGetSymbolAddress((void**)&xpl, g_xpl);
    cudaGetSymbolAddress((void**)&wpth, g_wpth);   cudaGetSymbolAddress((void**)&wptl, g_wptl);
    cudaGetSymbolAddress((void**)&wqkth, g_wqkth); cudaGetSymbolAddress((void**)&wqktl, g_wqktl);
    cudaGetSymbolAddress((void**)&wvth, g_wvth);   cudaGetSymbolAddress((void**)&wvtl, g_wvtl);
    cudaGetSymbolAddress((void**)&x0h, g_x0h);     cudaGetSymbolAddress((void**)&x0l, g_x0l);
    cudaGetSymbolAddress((void**)&x1h, g_x1h);     cudaGetSymbolAddress((void**)&x1l, g_x1l);
    cudaGetSymbolAddress((void**)&qkh, g_qkh);     cudaGetSymbolAddress((void**)&qkl, g_qkl);
    cudaGetSymbolAddress((void**)&vth, g_vth);     cudaGetSymbolAddress((void**)&vtl, g_vtl);
    cudaGetSymbolAddress((void**)&pph, g_ph);      cudaGetSymbolAddress((void**)&ppl, g_pl);

    const float scale = 1.f / sqrtf((float)NTOK);
    const long sTok = (long)NTOK * DIMN;
    const long sSc  = (long)NTOK * NTOK;
    const long sP   = (long)NTOK * NTOKP;
    const long sVT  = (long)DIMN * NTOKP;
    const long sQK  = (long)NTOK * NQK;
    const long sWL  = (long)DIMN * DIMN;     // src stride per layer
    const long sWQK = (long)NQK * DIMN;      // dst stride per layer (combined)

    // ---- upfront preprocessing ----
    ln1_patchify_kernel<<<dim3(NPATCH, BSZ), 256>>>(img, ln1_g, ln1_b);
    transconv_kernel<<<dim3(PD/32, DIMN/32, 1), dim3(32,8)>>>(Wp, PD, DIMN, DIMN, 0, wpth, wptl, PD, 0);
    // wq^T -> rows 0..383 of each layer's [768][384] block ; wk^T -> rows 384..767
    transconv_kernel<<<dim3(DIMN/32, DIMN/32, DEPTH), dim3(32,8)>>>(
        wq, DIMN, DIMN, DIMN, sWL, wqkth, wqktl, DIMN, sWQK);
    transconv_kernel<<<dim3(DIMN/32, DIMN/32, DEPTH), dim3(32,8)>>>(
        wk, DIMN, DIMN, DIMN, sWL, wqkth + (size_t)DIMN*DIMN, wqktl + (size_t)DIMN*DIMN, DIMN, sWQK);
    wvstat_kernel<<<dim3(DIMN, DEPTH), 128>>>(wv_raw);
    wvT_kernel<<<dim3(DIMN, DEPTH), 128>>>(wv_raw);

    // patch embed: tmp = xp @ Wp + bp
    tc_gemm<1><<<dim3(DIMN/128, MPAT/128, 1), NTHR, SMEM_BYTES>>>(
        xph, xpl, PD, 0, wpth, wptl, PD, 0, tmp, DIMN, 0,
        MPAT, DIMN, PD, 0.f, bp, nullptr, nullptr, 0, nullptr, nullptr, 0, 0);
    ln2_assemble_kernel<<<dim3(NTOK, BSZ), 128>>>(ln2_g, ln2_b, pos, cls);

    __nv_bfloat16 *curh = x0h, *curl = x0l;
    __nv_bfloat16 *nxth = x1h, *nxtl = x1l;
    const dim3 gQK(NQK/128, (MTOK + 127)/128, 1);            // (6,145)
    const dim3 gV(DIMN/128, (MTOK + 127)/128, 1);            // (3,145)
    const dim3 gSC((NTOK + 127)/128, (NTOK + 127)/128, BSZ); // (5,5,32)
    const dim3 gOUT(DIMN/128, (NTOK + 127)/128, BSZ);        // (3,5,32)

    for (int l = 0; l < DEPTH; l++) {
        const __nv_bfloat16* wqh = wqkth + (size_t)l * sWQK;
        const __nv_bfloat16* wql = wqktl + (size_t)l * sWQK;
        const __nv_bfloat16* wvh = wvth + (size_t)l * sWL;
        const __nv_bfloat16* wvl = wvtl + (size_t)l * sWL;

        // qk = x @ [wq | wk]  -> split planes [MTOK, 768]
        tc_gemm<3><<<gQK, NTHR, SMEM_BYTES>>>(
            curh, curl, DIMN, 0, wqh, wql, DIMN, 0, nullptr, 0, 0,
            MTOK, NQK, DIMN, 0.f, nullptr, nullptr, nullptr, 0, qkh, qkl, NQK, 0);
        // v = x @ wv -> fp32 vf + transposed planes vt
        tc_gemm<5><<<gV, NTHR, SMEM_BYTES>>>(
            curh, curl, DIMN, 0, wvh, wvl, DIMN, 0, vf, DIMN, 0,
            MTOK, DIMN, DIMN, 0.f, nullptr, nullptr, nullptr, 0, vth, vtl, 0, 0);
        // scores = scale * q @ k^T (batched; q=cols 0..383, k=cols 384..767 of qk)
        tc_gemm<2><<<gSC, NTHR, SMEM_BYTES>>>(
            qkh, qkl, NQK, sQK, qkh + 384, qkl + 384, NQK, sQK, sf, NTOK, sSc,
            NTOK, NTOK, DIMN, scale, nullptr, nullptr, nullptr, 0, nullptr, nullptr, 0, 0);
        // column softmax -> probs planes
        colsoftmax_kernel<<<dim3((NTOK + 255)/256, BSZ), 256>>>();
        // x_new = 0.5*(probs @ v - v) + 0.5*x  -> planes
        tc_gemm<4><<<gOUT, NTHR, SMEM_BYTES>>>(
            pph, ppl, NTOKP, sP, vth, vtl, NTOKP, sVT, vf, DIMN, sTok,
            NTOK, DIMN, NTOKP, 0.f, nullptr, curh, curl, sTok, nxth, nxtl, DIMN, sTok);

        __nv_bfloat16* th = curh; curh = nxth; nxth = th;
        __nv_bfloat16* tl = curl; curl = nxtl; nxtl = tl;
    }
    head_kernel<<<BSZ, 256>>>(curh, curl, Wh, bh, out);
}

// round 9
// speedup vs baseline: 1.7951x; 1.7951x over previous
#include <cuda_runtime.h>
#include <cuda_fp16.h>
#include <math.h>
#include <stdint.h>

#define BSZ    32
#define DIMN   384
#define NTOK   577
#define NTOKP  640
#define NPATCH 576
#define PD     768
#define DEPTH  12
#define NCLS   1000
#define EPSC   1e-5f
#define MTOK   (BSZ*NTOK)    // 18464
#define MPAT   (BSZ*NPATCH)  // 18432
#define NQK    768

// ===================== scratch (static device globals; zero-initialized) =====================
__device__ float g_tmp[(size_t)MPAT*DIMN];
__device__ float g_vf [(size_t)MTOK*DIMN];
__device__ float g_s  [(size_t)BSZ*NTOK*NTOK];
__device__ float g_wvstat[DEPTH*2*DIMN];

#define PLANE(name, sz) __device__ __align__(16) __half name[(size_t)(sz)]
PLANE(g_xph, (size_t)MPAT*PD);    PLANE(g_xpl, (size_t)MPAT*PD);
PLANE(g_wpth, DIMN*PD);           PLANE(g_wptl, DIMN*PD);
PLANE(g_wqkth, (size_t)DEPTH*NQK*DIMN); PLANE(g_wqktl, (size_t)DEPTH*NQK*DIMN);
PLANE(g_wvth, (size_t)DEPTH*DIMN*DIMN); PLANE(g_wvtl, (size_t)DEPTH*DIMN*DIMN);
PLANE(g_x0h, (size_t)MTOK*DIMN);  PLANE(g_x0l, (size_t)MTOK*DIMN);
PLANE(g_x1h, (size_t)MTOK*DIMN);  PLANE(g_x1l, (size_t)MTOK*DIMN);
PLANE(g_qkh, (size_t)MTOK*NQK);   PLANE(g_qkl, (size_t)MTOK*NQK);
PLANE(g_vth, (size_t)BSZ*DIMN*NTOKP); PLANE(g_vtl, (size_t)BSZ*DIMN*NTOKP);
PLANE(g_ph,  (size_t)BSZ*NTOK*NTOKP); PLANE(g_pl,  (size_t)BSZ*NTOK*NTOKP);

// ===================== small helpers =====================
__device__ __forceinline__ void bsplit(float f, __half& h, __half& l) {
    h = __float2half(f);
    l = __float2half(f - __half2float(h));
}

__device__ __forceinline__ float block_reduce_sum(float v, float* sbuf) {
    int tid = threadIdx.x;
    sbuf[tid] = v; __syncthreads();
    for (int s = blockDim.x >> 1; s > 0; s >>= 1) {
        if (tid < s) sbuf[tid] += sbuf[tid + s];
        __syncthreads();
    }
    float r = sbuf[0]; __syncthreads();
    return r;
}

__device__ __forceinline__ uint32_t smem_u32(const void* p) {
    uint32_t a;
    asm("{ .reg .u64 t; cvta.to.shared.u64 t, %1; cvt.u32.u64 %0, t; }" : "=r"(a) : "l"(p));
    return a;
}

__device__ __forceinline__ void mma_f16(float* c, const uint32_t* a, const uint32_t* b) {
    asm volatile(
        "mma.sync.aligned.m16n8k16.row.col.f32.f16.f16.f32 "
        "{%0,%1,%2,%3},{%4,%5,%6,%7},{%8,%9},{%0,%1,%2,%3};\n"
        : "+f"(c[0]), "+f"(c[1]), "+f"(c[2]), "+f"(c[3])
        : "r"(a[0]), "r"(a[1]), "r"(a[2]), "r"(a[3]), "r"(b[0]), "r"(b[1]));
}

__device__ __forceinline__ void ldsm4(uint32_t* r, uint32_t addr) {
    asm volatile("ldmatrix.sync.aligned.m8n8.x4.shared.b16 {%0,%1,%2,%3}, [%4];"
                 : "=r"(r[0]), "=r"(r[1]), "=r"(r[2]), "=r"(r[3]) : "r"(addr));
}

__device__ __forceinline__ void cpasync16(uint32_t dst, const void* src, int srcsize) {
    asm volatile("cp.async.cg.shared.global [%0], [%1], 16, %2;"
                 :: "r"(dst), "l"(src), "r"(srcsize) : "memory");
}
#define CP_COMMIT() asm volatile("cp.async.commit_group;" ::: "memory")
template<int NG> __device__ __forceinline__ void cp_wait() {
    asm volatile("cp.async.wait_group %0;" :: "n"(NG) : "memory");
}

// smem stage: 3 planes (Ah, Al, Bh), each 128 rows x 32 f16, pitch 40 f16 (80 B)
#define SPITCH    40
#define PLANE_B   (128 * SPITCH * 2)     // 10240
#define STAGE_B   (3 * PLANE_B)          // 30720
#define SMEM_BYTES 66048                 // max(2 stages = 61440, epilogue 128*129*4) -> 2 CTAs/SM

// ===================== fp16 split-A tensor GEMM (mma.sync) =====================
// C[M,N] = A[M,K] * B[N,K]^T ; A split hi/lo fp16 (2 products), B hi fp16 only.
// EPI: 1 fp32+bias, 2 fp32*alpha, 3 planes (Ph/Pl at ldp),
//      4 out: p = 0.5*(val - C[ix]) + 0.5*(Xh+Xl)[ip] -> planes only,
//      5 v: fp32 C + transposed hi plane vt[(b*DIMN+gn)*NTOKP + tok] (lo unused by consumer)
template<int EPI>
__global__ void __launch_bounds__(256)
tc_gemm(const __half* __restrict__ Ah, const __half* __restrict__ Al,
        int lda, long sA,
        const __half* __restrict__ Bh,
        int ldb, long sB,
        float* __restrict__ C, int ldc, long sC,
        int M, int N, int K, float alpha,
        const float* __restrict__ bias,
        const __half* __restrict__ Xh, const __half* __restrict__ Xl, long sX,
        __half* __restrict__ Ph, __half* __restrict__ Pl,
        int ldp, long sP)
{
    extern __shared__ char smem[];
    uint32_t sbase = smem_u32(smem);
    int tid = threadIdx.x, lane = tid & 31, wid = tid >> 5;
    int wm = wid >> 2, wn = wid & 3;       // warp tile 64x32 at (wm*64, wn*32)
    int z = blockIdx.z;
    Ah += (size_t)z * sA; Al += (size_t)z * sA;
    Bh += (size_t)z * sB;
    if (EPI == 1 || EPI == 2 || EPI == 4 || EPI == 5) C += (size_t)z * sC;
    if (EPI == 4) { Xh += (size_t)z * sX; Xl += (size_t)z * sX; }
    if (EPI == 3 || EPI == 4) { Ph += (size_t)z * sP; Pl += (size_t)z * sP; }
    int m0 = blockIdx.y * 128, n0 = blockIdx.x * 128;

    float acc[4][4][4];
    #pragma unroll
    for (int i = 0; i < 4; i++)
        #pragma unroll
        for (int j = 0; j < 4; j++)
            #pragma unroll
            for (int r = 0; r < 4; r++) acc[i][j][r] = 0.f;

    int arow = (lane & 7) + ((lane >> 3) & 1) * 8;
    int acol = (lane >> 4) * 8;
    int brow = (lane & 7) + ((lane >> 4) ? 8 : 0);
    int bcol = ((lane >> 3) & 1) * 8;

    auto stage_load = [&](int t) {
        uint32_t sb = sbase + (uint32_t)(t & 1) * STAGE_B;
        long k0 = (long)t * 32;
        #pragma unroll
        for (int it = 0; it < 2; it++) {
            int e = tid + it * 256;                  // 0..511
            int r = e >> 2, c4 = e & 3;
            uint32_t d = sb + (uint32_t)(r * (SPITCH*2) + c4 * 16);
            int gm = m0 + r;
            bool okA = gm < M;
            const char* pAh = (const char*)(Ah + (long)(okA ? gm : 0) * lda + k0) + c4 * 16;
            const char* pAl = (const char*)(Al + (long)(okA ? gm : 0) * lda + k0) + c4 * 16;
            cpasync16(d,             pAh, okA ? 16 : 0);
            cpasync16(d + PLANE_B,   pAl, okA ? 16 : 0);
            int gn = n0 + r;
            bool okB = gn < N;
            const char* pBh = (const char*)(Bh + (long)(okB ? gn : 0) * ldb + k0) + c4 * 16;
            cpasync16(d + 2*PLANE_B, pBh, okB ? 16 : 0);
        }
        CP_COMMIT();
    };

    auto compute = [&](int buf) {
        uint32_t sb = sbase + (uint32_t)buf * STAGE_B;
        uint32_t aAh = sb +             (uint32_t)((wm*64 + arow) * (SPITCH*2) + acol*2);
        uint32_t aAl = aAh + PLANE_B;
        uint32_t aBh = sb + 2*PLANE_B + (uint32_t)((wn*32 + brow) * (SPITCH*2) + bcol*2);
        #pragma unroll
        for (int s = 0; s < 2; s++) {
            uint32_t koff = (uint32_t)(s * 16 * 2);
            uint32_t ah[4][4], al[4][4];
            #pragma unroll
            for (int mt = 0; mt < 4; mt++) {
                uint32_t ro = (uint32_t)(mt * 16 * (SPITCH*2)) + koff;
                ldsm4(ah[mt], aAh + ro);
                ldsm4(al[mt], aAl + ro);
            }
            uint32_t bh2[2][4];
            #pragma unroll
            for (int np = 0; np < 2; np++) {
                uint32_t ro = (uint32_t)(np * 16 * (SPITCH*2)) + koff;
                ldsm4(bh2[np], aBh + ro);
            }
            // product-major: 16 independent MMAs between same-acc reuse
            #pragma unroll
            for (int mt = 0; mt < 4; mt++)
                #pragma unroll
                for (int nt = 0; nt < 4; nt++)
                    mma_f16(acc[mt][nt], ah[mt], &bh2[nt >> 1][(nt & 1) * 2]);
            #pragma unroll
            for (int mt = 0; mt < 4; mt++)
                #pragma unroll
                for (int nt = 0; nt < 4; nt++)
                    mma_f16(acc[mt][nt], al[mt], &bh2[nt >> 1][(nt & 1) * 2]);
        }
    };

    int nk = K / 32;
    stage_load(0);
    for (int t = 0; t < nk; t++) {
        if (t + 1 < nk) { stage_load(t + 1); cp_wait<1>(); }
        else            { cp_wait<0>(); }
        __syncthreads();
        compute(t & 1);
        __syncthreads();
    }

    // epilogue: regs -> smem (pitch 129 floats; conflict-free rows AND columns)
    float* sst = (float*)smem;
    int g = lane >> 2, tq = lane & 3;
    #pragma unroll
    for (int mt = 0; mt < 4; mt++)
        #pragma unroll
        for (int nt = 0; nt < 4; nt++)
            #pragma unroll
            for (int r = 0; r < 4; r++) {
                int m = wm*64 + mt*16 + g + ((r >= 2) ? 8 : 0);
                int n = wn*32 + nt*8 + 2*tq + (r & 1);
                sst[m * 129 + n] = acc[mt][nt][r];
            }
    __syncthreads();

    if (EPI == 1 || EPI == 2 || EPI == 3 || EPI == 4) {
        for (int e = tid; e < 16384; e += 256) {
            int r = e >> 7, c = e & 127;
            int gm = m0 + r, gn = n0 + c;
            if (gm >= M || gn >= N) continue;
            float val = sst[r * 129 + c];
            if (EPI == 1) {
                C[(long)gm * ldc + gn] = val + bias[gn];
            } else if (EPI == 2) {
                C[(long)gm * ldc + gn] = val * alpha;
            } else if (EPI == 3) {
                __half h, l; bsplit(val, h, l);
                long ip = (long)gm * ldp + gn;
                Ph[ip] = h; Pl[ip] = l;
            } else {  // EPI 4
                long ix = (long)gm * ldc + gn;
                long ip = (long)gm * ldp + gn;
                float xprev = __half2float(Xh[ip]) + __half2float(Xl[ip]);
                float v2 = 0.5f * (val - C[ix]) + 0.5f * xprev;
                __half h, l; bsplit(v2, h, l);
                Ph[ip] = h; Pl[ip] = l;
            }
        }
    } else {  // EPI 5: v — fp32 C plus transposed hi plane (lo plane not consumed)
        for (int e = tid; e < 16384; e += 256) {
            int r = e >> 7, c = e & 127;
            int gm = m0 + r, gn = n0 + c;
            if (gm >= M || gn >= N) continue;
            C[(long)gm * ldc + gn] = sst[r * 129 + c];
        }
        for (int e = tid; e < 16384; e += 256) {
            int c = e >> 7, r = e & 127;          // consecutive tid -> consecutive r (gm)
            int gm = m0 + r, gn = n0 + c;
            if (gm >= M || gn >= N) continue;
            float val = sst[r * 129 + c];
            int b = gm / NTOK, tok = gm - b * NTOK;
            long it = ((long)b * DIMN + gn) * NTOKP + tok;
            Ph[it] = __float2half(val);
        }
    }
}

// ===================== elementwise kernels =====================
__global__ void ln1_patchify_kernel(const float* __restrict__ img,
                                    const float* __restrict__ g1,
                                    const float* __restrict__ b1) {
    int p = blockIdx.x, b = blockIdx.y, tid = threadIdx.x;
    int phh = p / 24, pw = p % 24;
    __shared__ float sv[PD];
    __shared__ float sred[256];
    int pr = tid >> 4, pc = tid & 15;
    float s1 = 0.f, s2 = 0.f;
    #pragma unroll
    for (int c = 0; c < 3; c++) {
        float v = img[(((size_t)b*3 + c)*384 + (phh*16 + pr))*384 + (pw*16 + pc)];
        sv[(pr*16 + pc)*3 + c] = v;
        s1 += v; s2 += v*v;
    }
    float tot  = block_reduce_sum(s1, sred);
    float tot2 = block_reduce_sum(s2, sred);
    float mean = tot / PD;
    float var  = tot2 / PD - mean*mean;
    float rs   = rsqrtf(var + EPSC);
    size_t base = ((size_t)b*NPATCH + p)*PD;
    for (int d = tid; d < PD; d += 256) {
        float f = (sv[d] - mean)*rs*g1[d] + b1[d];
        __half h, l; bsplit(f, h, l);
        g_xph[base + d] = h; g_xpl[base + d] = l;
    }
}

__global__ void ln2_assemble_kernel(const float* __restrict__ g2,
                                    const float* __restrict__ b2,
                                    const float* __restrict__ pos,
                                    const float* __restrict__ cls) {
    int t = blockIdx.x, b = blockIdx.y, tid = threadIdx.x;
    size_t base = ((size_t)b*NTOK + t)*DIMN;
    if (t == 0) {
        for (int d = tid; d < DIMN; d += 128) {
            float f = cls[d] + pos[d];
            __half h, l; bsplit(f, h, l);
            g_x0h[base + d] = h; g_x0l[base + d] = l;
        }
        return;
    }
    __shared__ float sv[DIMN];
    __shared__ float sred[128];
    const float* in = g_tmp + ((size_t)b*NPATCH + (t-1))*DIMN;
    float s1 = 0.f, s2 = 0.f;
    for (int d = tid; d < DIMN; d += 128) { float v = in[d]; sv[d] = v; s1 += v; s2 += v*v; }
    float tot  = block_reduce_sum(s1, sred);
    float tot2 = block_reduce_sum(s2, sred);
    float mean = tot / DIMN;
    float var  = tot2 / DIMN - mean*mean;
    float rs   = rsqrtf(var + EPSC);
    for (int d = tid; d < DIMN; d += 128) {
        float f = (sv[d] - mean)*rs*g2[d] + b2[d] + pos[(size_t)t*DIMN + d];
        __half h, l; bsplit(f, h, l);
        g_x0h[base + d] = h; g_x0l[base + d] = l;
    }
}

// per-layer, per-column-k stats of lv (blockIdx.y = layer)
__global__ void wvstat_kernel(const float* __restrict__ wv_raw) {
    int k = blockIdx.x, l = blockIdx.y, tid = threadIdx.x;
    const float* lv = wv_raw + (size_t)l*DIMN*DIMN;
    __shared__ float sred[128];
    float mx = -1e30f;
    for (int a = tid; a < DIMN; a += 128) mx = fmaxf(mx, lv[(size_t)a*DIMN + k]);
    sred[tid] = mx; __syncthreads();
    for (int s = 64; s > 0; s >>= 1) { if (tid < s) sred[tid] = fmaxf(sred[tid], sred[tid+s]); __syncthreads(); }
    mx = sred[0]; __syncthreads();
    float sm = 0.f;
    for (int a = tid; a < DIMN; a += 128) sm += __expf(lv[(size_t)a*DIMN + k] - mx);
    float tot = block_reduce_sum(sm, sred);
    if (tid == 0) {
        g_wvstat[(size_t)l*2*DIMN + k] = mx;
        g_wvstat[(size_t)l*2*DIMN + DIMN + k] = 1.f / (tot * (float)DIMN);
    }
}

__global__ void wvT_kernel(const float* __restrict__ wv_raw) {
    int n = blockIdx.x, l = blockIdx.y, tid = threadIdx.x;
    const float* lv = wv_raw + (size_t)l*DIMN*DIMN;
    const float* st = g_wvstat + (size_t)l*2*DIMN;
    size_t ob = (size_t)l*DIMN*DIMN + (size_t)n*DIMN;
    for (int k = tid; k < DIMN; k += 128) {
        float f = __expf(lv[(size_t)n*DIMN + k] - st[k]) * st[DIMN + k];
        __half h, l2; bsplit(f, h, l2);
        g_wvth[ob + k] = h; g_wvtl[ob + k] = l2;
    }
}

// fp32 [R,C] -> fp16 hi/lo planes [C, Rpad] (zero-pad r>=R)
__global__ void transconv_kernel(const float* __restrict__ src, int R, int Cc, int pitch, long sZ,
                                 __half* __restrict__ dh, __half* __restrict__ dl,
                                 int Rpad, long dZ) {
    __shared__ float tile[32][33];
    int z = blockIdx.z;
    src += (size_t)z * sZ; dh += (size_t)z * dZ; dl += (size_t)z * dZ;
    int rb = blockIdx.x * 32, cb = blockIdx.y * 32;
    int tx = threadIdx.x, ty = threadIdx.y;   // 32 x 8
    #pragma unroll
    for (int i = 0; i < 4; i++) {
        int r = rb + ty + i*8, c = cb + tx;
        tile[ty + i*8][tx] = (r < R && c < Cc) ? src[(long)r*pitch + c] : 0.f;
    }
    __syncthreads();
    #pragma unroll
    for (int i = 0; i < 4; i++) {
        int dr = cb + ty + i*8;
        int dc = rb + tx;
        if (dr < Cc && dc < Rpad) {
            float f = tile[tx][ty + i*8];
            __half h, l; bsplit(f, h, l);
            dh[(long)dr*Rpad + dc] = h; dl[(long)dr*Rpad + dc] = l;
        }
    }
}

// column softmax over axis i -> probs planes [i][NTOKP] (pad cols stay zero-init)
// block 128 = 32 cols x 4 row-groups; grid (ceil(NTOK/32), BSZ)
__global__ void colsoftmax_kernel() {
    int b = blockIdx.y;
    int tx = threadIdx.x & 31, ty = threadIdx.x >> 5;
    int j = blockIdx.x * 32 + tx;
    __shared__ float sm_[4][32], ss_[4][32];
    const float* s = g_s + (size_t)b*NTOK*NTOK;
    float m = -1e30f, sum = 0.f;
    if (j < NTOK) {
        for (int i = ty; i < NTOK; i += 4) {
            float v = s[(size_t)i*NTOK + j];
            float nm = fmaxf(m, v);
            sum = sum * __expf(m - nm) + __expf(v - nm);
            m = nm;
        }
    }
    sm_[ty][tx] = m; ss_[ty][tx] = sum;
    __syncthreads();
    if (ty == 0) {
        float M = sm_[0][tx], S = ss_[0][tx];
        #pragma unroll
        for (int t2 = 1; t2 < 4; t2++) {
            float m2 = sm_[t2][tx], s2 = ss_[t2][tx];
            float nm = fmaxf(M, m2);
            S = S * __expf(M - nm) + s2 * __expf(m2 - nm);
            M = nm;
        }
        sm_[0][tx] = M; ss_[0][tx] = 1.f / S;
    }
    __syncthreads();
    if (j >= NTOK) return;
    float M = sm_[0][tx], inv = ss_[0][tx];
    __half* ph = g_ph + (size_t)b*NTOK*NTOKP;
    __half* pl = g_pl + (size_t)b*NTOK*NTOKP;
    for (int i = ty; i < NTOK; i += 4) {
        float p = __expf(s[(size_t)i*NTOK + j] - M) * inv;
        __half h, l; bsplit(p, h, l);
        ph[(size_t)i*NTOKP + j] = h;
        pl[(size_t)i*NTOKP + j] = l;
    }
}

__global__ void head_kernel(const __half* __restrict__ xh,
                            const __half* __restrict__ xl,
                            const float* __restrict__ Wh,
                            const float* __restrict__ bh,
                            float* __restrict__ out) {
    int b = blockIdx.x, tid = threadIdx.x;
    __shared__ float sx[DIMN];
    for (int d = tid; d < DIMN; d += 256) {
        size_t ix = (size_t)b*NTOK*DIMN + d;
        sx[d] = __half2float(xh[ix]) + __half2float(xl[ix]);
    }
    __syncthreads();
    for (int n = tid; n < NCLS; n += 256) {
        float acc = bh[n];
        #pragma unroll 4
        for (int kk = 0; kk < DIMN; kk++)
            acc += sx[kk] * Wh[(size_t)kk*NCLS + n];
        out[(size_t)b*NCLS + n] = acc;
    }
}

// ===================== launch =====================
extern "C" void kernel_launch(void* const* d_in, const int* in_sizes, int n_in,
                              void* d_out, int out_size) {
    const float* img    = (const float*)d_in[0];
    const float* ln1_g  = (const float*)d_in[1];
    const float* ln1_b  = (const float*)d_in[2];
    const float* Wp     = (const float*)d_in[3];
    const float* bp     = (const float*)d_in[4];
    const float* ln2_g  = (const float*)d_in[5];
    const float* ln2_b  = (const float*)d_in[6];
    const float* pos    = (const float*)d_in[7];
    const float* cls    = (const float*)d_in[8];
    const float* wk     = (const float*)d_in[9];
    const float* wq     = (const float*)d_in[10];
    const float* wv_raw = (const float*)d_in[11];
    const float* Wh     = (const float*)d_in[12];
    const float* bh     = (const float*)d_in[13];
    float* out = (float*)d_out;

    cudaFuncSetAttribute(tc_gemm<1>, cudaFuncAttributeMaxDynamicSharedMemorySize, SMEM_BYTES);
    cudaFuncSetAttribute(tc_gemm<2>, cudaFuncAttributeMaxDynamicSharedMemorySize, SMEM_BYTES);
    cudaFuncSetAttribute(tc_gemm<3>, cudaFuncAttributeMaxDynamicSharedMemorySize, SMEM_BYTES);
    cudaFuncSetAttribute(tc_gemm<4>, cudaFuncAttributeMaxDynamicSharedMemorySize, SMEM_BYTES);
    cudaFuncSetAttribute(tc_gemm<5>, cudaFuncAttributeMaxDynamicSharedMemorySize, SMEM_BYTES);

    float *tmp, *vf, *sf;
    cudaGetSymbolAddress((void**)&tmp, g_tmp);
    cudaGetSymbolAddress((void**)&vf,  g_vf);
    cudaGetSymbolAddress((void**)&sf,  g_s);
    __half *xph,*xpl,*wpth,*wptl,*wqkth,*wqktl,*wvth,*wvtl;
    __half *x0h,*x0l,*x1h,*x1l,*qkh,*qkl,*vth,*vtl,*pph,*ppl;
    cudaGetSymbolAddress((void**)&xph, g_xph);     cudaGetSymbolAddress((void**)&xpl, g_xpl);
    cudaGetSymbolAddress((void**)&wpth, g_wpth);   cudaGetSymbolAddress((void**)&wptl, g_wptl);
    cudaGetSymbolAddress((void**)&wqkth, g_wqkth); cudaGetSymbolAddress((void**)&wqktl, g_wqktl);
    cudaGetSymbolAddress((void**)&wvth, g_wvth);   cudaGetSymbolAddress((void**)&wvtl, g_wvtl);
    cudaGetSymbolAddress((void**)&x0h, g_x0h);     cudaGetSymbolAddress((void**)&x0l, g_x0l);
    cudaGetSymbolAddress((void**)&x1h, g_x1h);     cudaGetSymbolAddress((void**)&x1l, g_x1l);
    cudaGetSymbolAddress((void**)&qkh, g_qkh);     cudaGetSymbolAddress((void**)&qkl, g_qkl);
    cudaGetSymbolAddress((void**)&vth, g_vth);     cudaGetSymbolAddress((void**)&vtl, g_vtl);
    cudaGetSymbolAddress((void**)&pph, g_ph);      cudaGetSymbolAddress((void**)&ppl, g_pl);

    const float scale = 1.f / sqrtf((float)NTOK);
    const long sTok = (long)NTOK * DIMN;
    const long sSc  = (long)NTOK * NTOK;
    const long sP   = (long)NTOK * NTOKP;
    const long sVT  = (long)DIMN * NTOKP;
    const long sQK  = (long)NTOK * NQK;
    const long sWL  = (long)DIMN * DIMN;     // src stride per layer
    const long sWQK = (long)NQK * DIMN;      // dst stride per layer (combined)

    // ---- upfront preprocessing ----
    ln1_patchify_kernel<<<dim3(NPATCH, BSZ), 256>>>(img, ln1_g, ln1_b);
    transconv_kernel<<<dim3(PD/32, DIMN/32, 1), dim3(32,8)>>>(Wp, PD, DIMN, DIMN, 0, wpth, wptl, PD, 0);
    // wq^T -> rows 0..383 of each layer's [768][384] block ; wk^T -> rows 384..767
    transconv_kernel<<<dim3(DIMN/32, DIMN/32, DEPTH), dim3(32,8)>>>(
        wq, DIMN, DIMN, DIMN, sWL, wqkth, wqktl, DIMN, sWQK);
    transconv_kernel<<<dim3(DIMN/32, DIMN/32, DEPTH), dim3(32,8)>>>(
        wk, DIMN, DIMN, DIMN, sWL, wqkth + (size_t)DIMN*DIMN, wqktl + (size_t)DIMN*DIMN, DIMN, sWQK);
    wvstat_kernel<<<dim3(DIMN, DEPTH), 128>>>(wv_raw);
    wvT_kernel<<<dim3(DIMN, DEPTH), 128>>>(wv_raw);

    // patch embed: tmp = xp @ Wp + bp
    tc_gemm<1><<<dim3(DIMN/128, MPAT/128, 1), 256, SMEM_BYTES>>>(
        xph, xpl, PD, 0, wpth, PD, 0, tmp, DIMN, 0,
        MPAT, DIMN, PD, 0.f, bp, nullptr, nullptr, 0, nullptr, nullptr, 0, 0);
    ln2_assemble_kernel<<<dim3(NTOK, BSZ), 128>>>(ln2_g, ln2_b, pos, cls);

    __half *curh = x0h, *curl = x0l;
    __half *nxth = x1h, *nxtl = x1l;
    const dim3 gQK(NQK/128, (MTOK + 127)/128, 1);            // (6,145)
    const dim3 gV(DIMN/128, (MTOK + 127)/128, 1);            // (3,145)
    const dim3 gSC((NTOK + 127)/128, (NTOK + 127)/128, BSZ); // (5,5,32)
    const dim3 gOUT(DIMN/128, (NTOK + 127)/128, BSZ);        // (3,5,32)

    for (int l = 0; l < DEPTH; l++) {
        const __half* wqh = wqkth + (size_t)l * sWQK;
        const __half* wvh = wvth + (size_t)l * sWL;

        // qk = x @ [wq | wk]  -> split planes [MTOK, 768]
        tc_gemm<3><<<gQK, 256, SMEM_BYTES>>>(
            curh, curl, DIMN, 0, wqh, DIMN, 0, nullptr, 0, 0,
            MTOK, NQK, DIMN, 0.f, nullptr, nullptr, nullptr, 0, qkh, qkl, NQK, 0);
        // v = x @ wv -> fp32 vf + transposed hi plane vt
        tc_gemm<5><<<gV, 256, SMEM_BYTES>>>(
            curh, curl, DIMN, 0, wvh, DIMN, 0, vf, DIMN, 0,
            MTOK, DIMN, DIMN, 0.f, nullptr, nullptr, nullptr, 0, vth, vtl, 0, 0);
        // scores = scale * q @ k^T (batched; q=cols 0..383 split, k=cols 384..767 hi)
        tc_gemm<2><<<gSC, 256, SMEM_BYTES>>>(
            qkh, qkl, NQK, sQK, qkh + 384, NQK, sQK, sf, NTOK, sSc,
            NTOK, NTOK, DIMN, scale, nullptr, nullptr, nullptr, 0, nullptr, nullptr, 0, 0);
        // column softmax -> probs planes
        colsoftmax_kernel<<<dim3((NTOK + 31)/32, BSZ), 128>>>();
        // x_new = 0.5*(probs @ v - v) + 0.5*x  -> planes
        tc_gemm<4><<<gOUT, 256, SMEM_BYTES>>>(
            pph, ppl, NTOKP, sP, vth, NTOKP, sVT, vf, DIMN, sTok,
            NTOK, DIMN, NTOKP, 0.f, nullptr, curh, curl, sTok, nxth, nxtl, DIMN, sTok);

        __half* th = curh; curh = nxth; nxth = th;
        __half* tl = curl; curl = nxtl; nxtl = tl;
    }
    head_kernel<<<BSZ, 256>>>(curh, curl, Wh, bh, out);
}

// round 11
// speedup vs baseline: 2.3888x; 1.3308x over previous
#include <cuda_runtime.h>
#include <cuda_fp16.h>
#include <math.h>
#include <stdint.h>

#define BSZ    32
#define DIMN   384
#define NTOK   577
#define NTOKP  640
#define NPATCH 576
#define PD     768
#define DEPTH  12
#define NCLS   1000
#define EPSC   1e-5f
#define MTOK   (BSZ*NTOK)    // 18464
#define MPAT   (BSZ*NPATCH)  // 18432
#define NQK    768

// ===================== scratch (static device globals; zero-initialized) =====================
__device__ float g_tmp[(size_t)MPAT*DIMN];
__device__ float g_vf [(size_t)MTOK*DIMN];
__device__ float g_s  [(size_t)BSZ*NTOK*NTOK];
__device__ float g_wvstat[DEPTH*2*DIMN];

#define PLANE(name, sz) __device__ __align__(16) __half name[(size_t)(sz)]
PLANE(g_xph, (size_t)MPAT*PD);
PLANE(g_wpth, DIMN*PD);
PLANE(g_wqkth, (size_t)DEPTH*NQK*DIMN);
PLANE(g_wvth, (size_t)DEPTH*DIMN*DIMN);
PLANE(g_x0h, (size_t)MTOK*DIMN);  PLANE(g_x0l, (size_t)MTOK*DIMN);
PLANE(g_x1h, (size_t)MTOK*DIMN);  PLANE(g_x1l, (size_t)MTOK*DIMN);
PLANE(g_qkh, (size_t)MTOK*NQK);
PLANE(g_vth, (size_t)BSZ*DIMN*NTOKP);
PLANE(g_ph,  (size_t)BSZ*NTOK*NTOKP);

// ===================== small helpers =====================
__device__ __forceinline__ void bsplit(float f, __half& h, __half& l) {
    h = __float2half(f);
    l = __float2half(f - __half2float(h));
}

__device__ __forceinline__ float block_reduce_sum(float v, float* sbuf) {
    int tid = threadIdx.x;
    sbuf[tid] = v; __syncthreads();
    for (int s = blockDim.x >> 1; s > 0; s >>= 1) {
        if (tid < s) sbuf[tid] += sbuf[tid + s];
        __syncthreads();
    }
    float r = sbuf[0]; __syncthreads();
    return r;
}

__device__ __forceinline__ uint32_t smem_u32(const void* p) {
    uint32_t a;
    asm("{ .reg .u64 t; cvta.to.shared.u64 t, %1; cvt.u32.u64 %0, t; }" : "=r"(a) : "l"(p));
    return a;
}

__device__ __forceinline__ void mma_f16(float* c, const uint32_t* a, const uint32_t* b) {
    asm volatile(
        "mma.sync.aligned.m16n8k16.row.col.f32.f16.f16.f32 "
        "{%0,%1,%2,%3},{%4,%5,%6,%7},{%8,%9},{%0,%1,%2,%3};\n"
        : "+f"(c[0]), "+f"(c[1]), "+f"(c[2]), "+f"(c[3])
        : "r"(a[0]), "r"(a[1]), "r"(a[2]), "r"(a[3]), "r"(b[0]), "r"(b[1]));
}

__device__ __forceinline__ void ldsm4(uint32_t* r, uint32_t addr) {
    asm volatile("ldmatrix.sync.aligned.m8n8.x4.shared.b16 {%0,%1,%2,%3}, [%4];"
                 : "=r"(r[0]), "=r"(r[1]), "=r"(r[2]), "=r"(r[3]) : "r"(addr));
}

__device__ __forceinline__ void cpasync16(uint32_t dst, const void* src, int srcsize) {
    asm volatile("cp.async.cg.shared.global [%0], [%1], 16, %2;"
                 :: "r"(dst), "l"(src), "r"(srcsize) : "memory");
}
#define CP_COMMIT() asm volatile("cp.async.commit_group;" ::: "memory")
template<int NG> __device__ __forceinline__ void cp_wait() {
    asm volatile("cp.async.wait_group %0;" :: "n"(NG) : "memory");
}

// smem stage: 2 planes (Ah, Bh), each 128 rows x 32 f16, pitch 40 f16 (80 B)
#define SPITCH    40
#define PLANE_B   (128 * SPITCH * 2)     // 10240
#define STAGE_B   (2 * PLANE_B)          // 20480
#define SMEM_BYTES 66048                 // max(2 stages = 40960, epilogue 128*129*4) -> 2 CTAs/SM

// ===================== fp16 single-product tensor GEMM (mma.sync) =====================
// C[M,N] = A[M,K] * B[N,K]^T ; A, B fp16, K-major, K mult of 32, rows 16B-aligned.
// EPI: 1 fp32+bias, 2 fp32*alpha, 3 hi plane (Ph at ldp),
//      4 out: p = 0.5*(val - C[ix]) + 0.5*(Xh+Xl)[ip] -> hi/lo planes,
//      5 v: fp32 C + transposed hi plane vt[(b*DIMN+gn)*NTOKP + tok]
template<int EPI>
__global__ void __launch_bounds__(256)
tc_gemm(const __half* __restrict__ Ah, int lda, long sA,
        const __half* __restrict__ Bh, int ldb, long sB,
        float* __restrict__ C, int ldc, long sC,
        int M, int N, int K, float alpha,
        const float* __restrict__ bias,
        const __half* __restrict__ Xh, const __half* __restrict__ Xl, long sX,
        __half* __restrict__ Ph, __half* __restrict__ Pl,
        int ldp, long sP)
{
    extern __shared__ char smem[];
    uint32_t sbase = smem_u32(smem);
    int tid = threadIdx.x, lane = tid & 31, wid = tid >> 5;
    int wm = wid >> 2, wn = wid & 3;       // warp tile 64x32 at (wm*64, wn*32)
    int z = blockIdx.z;
    Ah += (size_t)z * sA;
    Bh += (size_t)z * sB;
    if (EPI == 1 || EPI == 2 || EPI == 4 || EPI == 5) C += (size_t)z * sC;
    if (EPI == 4) { Xh += (size_t)z * sX; Xl += (size_t)z * sX; }
    if (EPI == 3 || EPI == 4) { Ph += (size_t)z * sP; if (EPI == 4) Pl += (size_t)z * sP; }
    int m0 = blockIdx.y * 128, n0 = blockIdx.x * 128;

    float acc[4][4][4];
    #pragma unroll
    for (int i = 0; i < 4; i++)
        #pragma unroll
        for (int j = 0; j < 4; j++)
            #pragma unroll
            for (int r = 0; r < 4; r++) acc[i][j][r] = 0.f;

    int arow = (lane & 7) + ((lane >> 3) & 1) * 8;
    int acol = (lane >> 4) * 8;
    int brow = (lane & 7) + ((lane >> 4) ? 8 : 0);
    int bcol = ((lane >> 3) & 1) * 8;

    auto stage_load = [&](int t) {
        uint32_t sb = sbase + (uint32_t)(t & 1) * STAGE_B;
        long k0 = (long)t * 32;
        #pragma unroll
        for (int it = 0; it < 2; it++) {
            int e = tid + it * 256;                  // 0..511
            int r = e >> 2, c4 = e & 3;
            uint32_t d = sb + (uint32_t)(r * (SPITCH*2) + c4 * 16);
            int gm = m0 + r;
            bool okA = gm < M;
            const char* pAh = (const char*)(Ah + (long)(okA ? gm : 0) * lda + k0) + c4 * 16;
            cpasync16(d,           pAh, okA ? 16 : 0);
            int gn = n0 + r;
            bool okB = gn < N;
            const char* pBh = (const char*)(Bh + (long)(okB ? gn : 0) * ldb + k0) + c4 * 16;
            cpasync16(d + PLANE_B, pBh, okB ? 16 : 0);
        }
        CP_COMMIT();
    };

    auto compute = [&](int buf) {
        uint32_t sb = sbase + (uint32_t)buf * STAGE_B;
        uint32_t aAh = sb +           (uint32_t)((wm*64 + arow) * (SPITCH*2) + acol*2);
        uint32_t aBh = sb + PLANE_B + (uint32_t)((wn*32 + brow) * (SPITCH*2) + bcol*2);
        #pragma unroll
        for (int s = 0; s < 2; s++) {
            uint32_t koff = (uint32_t)(s * 16 * 2);
            uint32_t ah[4][4];
            #pragma unroll
            for (int mt = 0; mt < 4; mt++) {
                uint32_t ro = (uint32_t)(mt * 16 * (SPITCH*2)) + koff;
                ldsm4(ah[mt], aAh + ro);
            }
            uint32_t bh2[2][4];
            #pragma unroll
            for (int np = 0; np < 2; np++) {
                uint32_t ro = (uint32_t)(np * 16 * (SPITCH*2)) + koff;
                ldsm4(bh2[np], aBh + ro);
            }
            #pragma unroll
            for (int mt = 0; mt < 4; mt++)
                #pragma unroll
                for (int nt = 0; nt < 4; nt++)
                    mma_f16(acc[mt][nt], ah[mt], &bh2[nt >> 1][(nt & 1) * 2]);
        }
    };

    int nk = K / 32;
    stage_load(0);
    for (int t = 0; t < nk; t++) {
        if (t + 1 < nk) { stage_load(t + 1); cp_wait<1>(); }
        else            { cp_wait<0>(); }
        __syncthreads();
        compute(t & 1);
        __syncthreads();
    }

    // epilogue: regs -> smem (pitch 129 floats; conflict-free rows AND columns)
    float* sst = (float*)smem;
    int g = lane >> 2, tq = lane & 3;
    #pragma unroll
    for (int mt = 0; mt < 4; mt++)
        #pragma unroll
        for (int nt = 0; nt < 4; nt++)
            #pragma unroll
            for (int r = 0; r < 4; r++) {
                int m = wm*64 + mt*16 + g + ((r >= 2) ? 8 : 0);
                int n = wn*32 + nt*8 + 2*tq + (r & 1);
                sst[m * 129 + n] = acc[mt][nt][r];
            }
    __syncthreads();

    if (EPI == 1 || EPI == 2 || EPI == 3 || EPI == 4) {
        for (int e = tid; e < 16384; e += 256) {
            int r = e >> 7, c = e & 127;
            int gm = m0 + r, gn = n0 + c;
            if (gm >= M || gn >= N) continue;
            float val = sst[r * 129 + c];
            if (EPI == 1) {
                C[(long)gm * ldc + gn] = val + bias[gn];
            } else if (EPI == 2) {
                C[(long)gm * ldc + gn] = val * alpha;
            } else if (EPI == 3) {
                Ph[(long)gm * ldp + gn] = __float2half(val);
            } else {  // EPI 4
                long ix = (long)gm * ldc + gn;
                long ip = (long)gm * ldp + gn;
                float xprev = __half2float(Xh[ip]) + __half2float(Xl[ip]);
                float v2 = 0.5f * (val - C[ix]) + 0.5f * xprev;
                __half h, l; bsplit(v2, h, l);
                Ph[ip] = h; Pl[ip] = l;
            }
        }
    } else {  // EPI 5: v — fp32 C plus transposed hi plane
        for (int e = tid; e < 16384; e += 256) {
            int r = e >> 7, c = e & 127;
            int gm = m0 + r, gn = n0 + c;
            if (gm >= M || gn >= N) continue;
            C[(long)gm * ldc + gn] = sst[r * 129 + c];
        }
        for (int e = tid; e < 16384; e += 256) {
            int c = e >> 7, r = e & 127;          // consecutive tid -> consecutive r (gm)
            int gm = m0 + r, gn = n0 + c;
            if (gm >= M || gn >= N) continue;
            float val = sst[r * 129 + c];
            int b = gm / NTOK, tok = gm - b * NTOK;
            long it = ((long)b * DIMN + gn) * NTOKP + tok;
            Ph[it] = __float2half(val);
        }
    }
}

// ===================== elementwise kernels =====================
__global__ void ln1_patchify_kernel(const float* __restrict__ img,
                                    const float* __restrict__ g1,
                                    const float* __restrict__ b1) {
    int p = blockIdx.x, b = blockIdx.y, tid = threadIdx.x;
    int phh = p / 24, pw = p % 24;
    __shared__ float sv[PD];
    __shared__ float sred[256];
    int pr = tid >> 4, pc = tid & 15;
    float s1 = 0.f, s2 = 0.f;
    #pragma unroll
    for (int c = 0; c < 3; c++) {
        float v = img[(((size_t)b*3 + c)*384 + (phh*16 + pr))*384 + (pw*16 + pc)];
        sv[(pr*16 + pc)*3 + c] = v;
        s1 += v; s2 += v*v;
    }
    float tot  = block_reduce_sum(s1, sred);
    float tot2 = block_reduce_sum(s2, sred);
    float mean = tot / PD;
    float var  = tot2 / PD - mean*mean;
    float rs   = rsqrtf(var + EPSC);
    size_t base = ((size_t)b*NPATCH + p)*PD;
    for (int d = tid; d < PD; d += 256)
        g_xph[base + d] = __float2half((sv[d] - mean)*rs*g1[d] + b1[d]);
}

__global__ void ln2_assemble_kernel(const float* __restrict__ g2,
                                    const float* __restrict__ b2,
                                    const float* __restrict__ pos,
                                    const float* __restrict__ cls) {
    int t = blockIdx.x, b = blockIdx.y, tid = threadIdx.x;
    size_t base = ((size_t)b*NTOK + t)*DIMN;
    if (t == 0) {
        for (int d = tid; d < DIMN; d += 128) {
            float f = cls[d] + pos[d];
            __half h, l; bsplit(f, h, l);
            g_x0h[base + d] = h; g_x0l[base + d] = l;
        }
        return;
    }
    __shared__ float sv[DIMN];
    __shared__ float sred[128];
    const float* in = g_tmp + ((size_t)b*NPATCH + (t-1))*DIMN;
    float s1 = 0.f, s2 = 0.f;
    for (int d = tid; d < DIMN; d += 128) { float v = in[d]; sv[d] = v; s1 += v; s2 += v*v; }
    float tot  = block_reduce_sum(s1, sred);
    float tot2 = block_reduce_sum(s2, sred);
    float mean = tot / DIMN;
    float var  = tot2 / DIMN - mean*mean;
    float rs   = rsqrtf(var + EPSC);
    for (int d = tid; d < DIMN; d += 128) {
        float f = (sv[d] - mean)*rs*g2[d] + b2[d] + pos[(size_t)t*DIMN + d];
        __half h, l; bsplit(f, h, l);
        g_x0h[base + d] = h; g_x0l[base + d] = l;
    }
}

// per-layer, per-column-k stats of lv (blockIdx.y = layer)
__global__ void wvstat_kernel(const float* __restrict__ wv_raw) {
    int k = blockIdx.x, l = blockIdx.y, tid = threadIdx.x;
    const float* lv = wv_raw + (size_t)l*DIMN*DIMN;
    __shared__ float sred[128];
    float mx = -1e30f;
    for (int a = tid; a < DIMN; a += 128) mx = fmaxf(mx, lv[(size_t)a*DIMN + k]);
    sred[tid] = mx; __syncthreads();
    for (int s = 64; s > 0; s >>= 1) { if (tid < s) sred[tid] = fmaxf(sred[tid], sred[tid+s]); __syncthreads(); }
    mx = sred[0]; __syncthreads();
    float sm = 0.f;
    for (int a = tid; a < DIMN; a += 128) sm += __expf(lv[(size_t)a*DIMN + k] - mx);
    float tot = block_reduce_sum(sm, sred);
    if (tid == 0) {
        g_wvstat[(size_t)l*2*DIMN + k] = mx;
        g_wvstat[(size_t)l*2*DIMN + DIMN + k] = 1.f / (tot * (float)DIMN);
    }
}

__global__ void wvT_kernel(const float* __restrict__ wv_raw) {
    int n = blockIdx.x, l = blockIdx.y, tid = threadIdx.x;
    const float* lv = wv_raw + (size_t)l*DIMN*DIMN;
    const float* st = g_wvstat + (size_t)l*2*DIMN;
    size_t ob = (size_t)l*DIMN*DIMN + (size_t)n*DIMN;
    for (int k = tid; k < DIMN; k += 128)
        g_wvth[ob + k] = __float2half(__expf(lv[(size_t)n*DIMN + k] - st[k]) * st[DIMN + k]);
}

// fp32 [R,C] -> fp16 plane [C, Rpad] (zero-pad r>=R)
__global__ void transconv_kernel(const float* __restrict__ src, int R, int Cc, int pitch, long sZ,
                                 __half* __restrict__ dh, int Rpad, long dZ) {
    __shared__ float tile[32][33];
    int z = blockIdx.z;
    src += (size_t)z * sZ; dh += (size_t)z * dZ;
    int rb = blockIdx.x * 32, cb = blockIdx.y * 32;
    int tx = threadIdx.x, ty = threadIdx.y;   // 32 x 8
    #pragma unroll
    for (int i = 0; i < 4; i++) {
        int r = rb + ty + i*8, c = cb + tx;
        tile[ty + i*8][tx] = (r < R && c < Cc) ? src[(long)r*pitch + c] : 0.f;
    }
    __syncthreads();
    #pragma unroll
    for (int i = 0; i < 4; i++) {
        int dr = cb + ty + i*8;
        int dc = rb + tx;
        if (dr < Cc && dc < Rpad)
            dh[(long)dr*Rpad + dc] = __float2half(tile[tx][ty + i*8]);
    }
}

// column softmax over axis i -> probs hi plane [i][NTOKP] (pad cols stay zero-init)
// block 128 = 32 cols x 4 row-groups; grid (ceil(NTOK/32), BSZ)
__global__ void colsoftmax_kernel() {
    int b = blockIdx.y;
    int tx = threadIdx.x & 31, ty = threadIdx.x >> 5;
    int j = blockIdx.x * 32 + tx;
    __shared__ float sm_[4][32], ss_[4][32];
    const float* s = g_s + (size_t)b*NTOK*NTOK;
    float m = -1e30f, sum = 0.f;
    if (j < NTOK) {
        for (int i = ty; i < NTOK; i += 4) {
            float v = s[(size_t)i*NTOK + j];
            float nm = fmaxf(m, v);
            sum = sum * __expf(m - nm) + __expf(v - nm);
            m = nm;
        }
    }
    sm_[ty][tx] = m; ss_[ty][tx] = sum;
    __syncthreads();
    if (ty == 0) {
        float M = sm_[0][tx], S = ss_[0][tx];
        #pragma unroll
        for (int t2 = 1; t2 < 4; t2++) {
            float m2 = sm_[t2][tx], s2 = ss_[t2][tx];
            float nm = fmaxf(M, m2);
            S = S * __expf(M - nm) + s2 * __expf(m2 - nm);
            M = nm;
        }
        sm_[0][tx] = M; ss_[0][tx] = 1.f / S;
    }
    __syncthreads();
    if (j >= NTOK) return;
    float M = sm_[0][tx], inv = ss_[0][tx];
    __half* ph = g_ph + (size_t)b*NTOK*NTOKP;
    for (int i = ty; i < NTOK; i += 4)
        ph[(size_t)i*NTOKP + j] = __float2half(__expf(s[(size_t)i*NTOK + j] - M) * inv);
}

__global__ void head_kernel(const __half* __restrict__ xh,
                            const __half* __restrict__ xl,
                            const float* __restrict__ Wh,
                            const float* __restrict__ bh,
                            float* __restrict__ out) {
    int b = blockIdx.x, tid = threadIdx.x;
    __shared__ float sx[DIMN];
    for (int d = tid; d < DIMN; d += 256) {
        size_t ix = (size_t)b*NTOK*DIMN + d;
        sx[d] = __half2float(xh[ix]) + __half2float(xl[ix]);
    }
    __syncthreads();
    for (int n = tid; n < NCLS; n += 256) {
        float acc = bh[n];
        #pragma unroll 4
        for (int kk = 0; kk < DIMN; kk++)
            acc += sx[kk] * Wh[(size_t)kk*NCLS + n];
        out[(size_t)b*NCLS + n] = acc;
    }
}

// ===================== launch =====================
extern "C" void kernel_launch(void* const* d_in, const int* in_sizes, int n_in,
                              void* d_out, int out_size) {
    const float* img    = (const float*)d_in[0];
    const float* ln1_g  = (const float*)d_in[1];
    const float* ln1_b  = (const float*)d_in[2];
    const float* Wp     = (const float*)d_in[3];
    const float* bp     = (const float*)d_in[4];
    const float* ln2_g  = (const float*)d_in[5];
    const float* ln2_b  = (const float*)d_in[6];
    const float* pos    = (const float*)d_in[7];
    const float* cls    = (const float*)d_in[8];
    const float* wk     = (const float*)d_in[9];
    const float* wq     = (const float*)d_in[10];
    const float* wv_raw = (const float*)d_in[11];
    const float* Wh     = (const float*)d_in[12];
    const float* bh     = (const float*)d_in[13];
    float* out = (float*)d_out;

    cudaFuncSetAttribute(tc_gemm<1>, cudaFuncAttributeMaxDynamicSharedMemorySize, SMEM_BYTES);
    cudaFuncSetAttribute(tc_gemm<2>, cudaFuncAttributeMaxDynamicSharedMemorySize, SMEM_BYTES);
    cudaFuncSetAttribute(tc_gemm<3>, cudaFuncAttributeMaxDynamicSharedMemorySize, SMEM_BYTES);
    cudaFuncSetAttribute(tc_gemm<4>, cudaFuncAttributeMaxDynamicSharedMemorySize, SMEM_BYTES);
    cudaFuncSetAttribute(tc_gemm<5>, cudaFuncAttributeMaxDynamicSharedMemorySize, SMEM_BYTES);

    float *tmp, *vf, *sf;
    cudaGetSymbolAddress((void**)&tmp, g_tmp);
    cudaGetSymbolAddress((void**)&vf,  g_vf);
    cudaGetSymbolAddress((void**)&sf,  g_s);
    __half *xph,*wpth,*wqkth,*wvth;
    __half *x0h,*x0l,*x1h,*x1l,*qkh,*vth,*pph;
    cudaGetSymbolAddress((void**)&xph, g_xph);
    cudaGetSymbolAddress((void**)&wpth, g_wpth);
    cudaGetSymbolAddress((void**)&wqkth, g_wqkth);
    cudaGetSymbolAddress((void**)&wvth, g_wvth);
    cudaGetSymbolAddress((void**)&x0h, g_x0h);     cudaGetSymbolAddress((void**)&x0l, g_x0l);
    cudaGetSymbolAddress((void**)&x1h, g_x1h);     cudaGetSymbolAddress((void**)&x1l, g_x1l);
    cudaGetSymbolAddress((void**)&qkh, g_qkh);
    cudaGetSymbolAddress((void**)&vth, g_vth);
    cudaGetSymbolAddress((void**)&pph, g_ph);

    const float scale = 1.f / sqrtf((float)NTOK);
    const long sTok = (long)NTOK * DIMN;
    const long sSc  = (long)NTOK * NTOK;
    const long sP   = (long)NTOK * NTOKP;
    const long sVT  = (long)DIMN * NTOKP;
    const long sQK  = (long)NTOK * NQK;
    const long sWL  = (long)DIMN * DIMN;     // src stride per layer
    const long sWQK = (long)NQK * DIMN;      // dst stride per layer (combined)

    // ---- upfront preprocessing ----
    ln1_patchify_kernel<<<dim3(NPATCH, BSZ), 256>>>(img, ln1_g, ln1_b);
    transconv_kernel<<<dim3(PD/32, DIMN/32, 1), dim3(32,8)>>>(Wp, PD, DIMN, DIMN, 0, wpth, PD, 0);
    // wq^T -> rows 0..383 of each layer's [768][384] block ; wk^T -> rows 384..767
    transconv_kernel<<<dim3(DIMN/32, DIMN/32, DEPTH), dim3(32,8)>>>(
        wq, DIMN, DIMN, DIMN, sWL, wqkth, DIMN, sWQK);
    transconv_kernel<<<dim3(DIMN/32, DIMN/32, DEPTH), dim3(32,8)>>>(
        wk, DIMN, DIMN, DIMN, sWL, wqkth + (size_t)DIMN*DIMN, DIMN, sWQK);
    wvstat_kernel<<<dim3(DIMN, DEPTH), 128>>>(wv_raw);
    wvT_kernel<<<dim3(DIMN, DEPTH), 128>>>(wv_raw);

    // patch embed: tmp = xp @ Wp + bp
    tc_gemm<1><<<dim3(DIMN/128, MPAT/128, 1), 256, SMEM_BYTES>>>(
        xph, PD, 0, wpth, PD, 0, tmp, DIMN, 0,
        MPAT, DIMN, PD, 0.f, bp, nullptr, nullptr, 0, nullptr, nullptr, 0, 0);
    ln2_assemble_kernel<<<dim3(NTOK, BSZ), 128>>>(ln2_g, ln2_b, pos, cls);

    __half *curh = x0h, *curl = x0l;
    __half *nxth = x1h, *nxtl = x1l;
    const dim3 gQK(NQK/128, (MTOK + 127)/128, 1);            // (6,145)
    const dim3 gV(DIMN/128, (MTOK + 127)/128, 1);            // (3,145)
    const dim3 gSC((NTOK + 127)/128, (NTOK + 127)/128, BSZ); // (5,5,32)
    const dim3 gOUT(DIMN/128, (NTOK + 127)/128, BSZ);        // (3,5,32)

    for (int l = 0; l < DEPTH; l++) {
        const __half* wqh = wqkth + (size_t)l * sWQK;
        const __half* wvh = wvth + (size_t)l * sWL;

        // qk = x @ [wq | wk]  -> hi plane [MTOK, 768]
        tc_gemm<3><<<gQK, 256, SMEM_BYTES>>>(
            curh, DIMN, 0, wqh, DIMN, 0, nullptr, 0, 0,
            MTOK, NQK, DIMN, 0.f, nullptr, nullptr, nullptr, 0, qkh, nullptr, NQK, 0);
        // v = x @ wv -> fp32 vf + transposed hi plane vt
        tc_gemm<5><<<gV, 256, SMEM_BYTES>>>(
            curh, DIMN, 0, wvh, DIMN, 0, vf, DIMN, 0,
            MTOK, DIMN, DIMN, 0.f, nullptr, nullptr, nullptr, 0, vth, nullptr, 0, 0);
        // scores = scale * q @ k^T (batched; q=cols 0..383, k=cols 384..767 of qk)
        tc_gemm<2><<<gSC, 256, SMEM_BYTES>>>(
            qkh, NQK, sQK, qkh + 384, NQK, sQK, sf, NTOK, sSc,
            NTOK, NTOK, DIMN, scale, nullptr, nullptr, nullptr, 0, nullptr, nullptr, 0, 0);
        // column softmax -> probs hi plane
        colsoftmax_kernel<<<dim3((NTOK + 31)/32, BSZ), 128>>>();
        // x_new = 0.5*(probs @ v - v) + 0.5*x  -> hi/lo planes
        tc_gemm<4><<<gOUT, 256, SMEM_BYTES>>>(
            pph, NTOKP, sP, vth, NTOKP, sVT, vf, DIMN, sTok,
            NTOK, DIMN, NTOKP, 0.f, nullptr, curh, curl, sTok, nxth, nxtl, DIMN, sTok);

        __half* th = curh; curh = nxth; nxth = th;
        __half* tl = curl; curl = nxtl; nxtl = tl;
    }
    head_kernel<<<BSZ, 256>>>(curh, curl, Wh, bh, out);
}

// round 13
// speedup vs baseline: 2.4123x; 1.0098x over previous
#include <cuda_runtime.h>
#include <cuda_fp16.h>
#include <math.h>
#include <stdint.h>

#define BSZ    32
#define DIMN   384
#define NTOK   577
#define NTOKP  640
#define NPATCH 576
#define PD     768
#define DEPTH  12
#define NCLS   1000
#define EPSC   1e-5f
#define MTOK   (BSZ*NTOK)    // 18464
#define MPAT   (BSZ*NPATCH)  // 18432
#define NQK    768
#define NQKV   1152

// ===================== scratch (static device globals; zero-initialized) =====================
__device__ float g_tmp[(size_t)MPAT*DIMN];
__device__ float g_vf [(size_t)MTOK*DIMN];
__device__ float g_wvstat[DEPTH*2*DIMN];

#define PLANE(name, sz) __device__ __align__(16) __half name[(size_t)(sz)]
PLANE(g_s,   (size_t)BSZ*NTOK*NTOK);           // fp16 scores
PLANE(g_xph, (size_t)MPAT*PD);
PLANE(g_wpth, DIMN*PD);
PLANE(g_wqkvth, (size_t)DEPTH*NQKV*DIMN);      // [wq^T | wk^T | wv_eff^T] per layer
PLANE(g_x0h, (size_t)MTOK*DIMN);  PLANE(g_x0l, (size_t)MTOK*DIMN);
PLANE(g_x1h, (size_t)MTOK*DIMN);  PLANE(g_x1l, (size_t)MTOK*DIMN);
PLANE(g_qkh, (size_t)MTOK*NQK);
PLANE(g_vth, (size_t)BSZ*DIMN*NTOKP);
PLANE(g_ph,  (size_t)BSZ*NTOK*NTOKP);

// ===================== small helpers =====================
__device__ __forceinline__ void bsplit(float f, __half& h, __half& l) {
    h = __float2half(f);
    l = __float2half(f - __half2float(h));
}

__device__ __forceinline__ float block_reduce_sum(float v, float* sbuf) {
    int tid = threadIdx.x;
    sbuf[tid] = v; __syncthreads();
    for (int s = blockDim.x >> 1; s > 0; s >>= 1) {
        if (tid < s) sbuf[tid] += sbuf[tid + s];
        __syncthreads();
    }
    float r = sbuf[0]; __syncthreads();
    return r;
}

__device__ __forceinline__ uint32_t smem_u32(const void* p) {
    uint32_t a;
    asm("{ .reg .u64 t; cvta.to.shared.u64 t, %1; cvt.u32.u64 %0, t; }" : "=r"(a) : "l"(p));
    return a;
}

__device__ __forceinline__ void mma_f16(float* c, const uint32_t* a, const uint32_t* b) {
    asm volatile(
        "mma.sync.aligned.m16n8k16.row.col.f32.f16.f16.f32 "
        "{%0,%1,%2,%3},{%4,%5,%6,%7},{%8,%9},{%0,%1,%2,%3};\n"
        : "+f"(c[0]), "+f"(c[1]), "+f"(c[2]), "+f"(c[3])
        : "r"(a[0]), "r"(a[1]), "r"(a[2]), "r"(a[3]), "r"(b[0]), "r"(b[1]));
}

__device__ __forceinline__ void ldsm4(uint32_t* r, uint32_t addr) {
    asm volatile("ldmatrix.sync.aligned.m8n8.x4.shared.b16 {%0,%1,%2,%3}, [%4];"
                 : "=r"(r[0]), "=r"(r[1]), "=r"(r[2]), "=r"(r[3]) : "r"(addr));
}

__device__ __forceinline__ void cpasync16(uint32_t dst, const void* src, int srcsize) {
    asm volatile("cp.async.cg.shared.global [%0], [%1], 16, %2;"
                 :: "r"(dst), "l"(src), "r"(srcsize) : "memory");
}
#define CP_COMMIT() asm volatile("cp.async.commit_group;" ::: "memory")
template<int NG> __device__ __forceinline__ void cp_wait() {
    asm volatile("cp.async.wait_group %0;" :: "n"(NG) : "memory");
}

// smem stage = TWO k32 sub-buffers, each 2 planes (Ah, Bh) of 128 rows x 32 f16, pitch 40 f16
#define SPITCH    40
#define PLANE_B   (128 * SPITCH * 2)     // 10240
#define SUB_B     (2 * PLANE_B)          // 20480 (one k32 sub-buffer)
#define STAGE_B   (2 * SUB_B)            // 40960 (k64 per sync)
#define SMEM_BYTES 81920                 // 2 stages; epilogue 128*129*4=66048 fits; 2 CTAs/SM

// ===================== fp16 single-product tensor GEMM (mma.sync), K-step 64 =====================
// C[M,N] = A[M,K] * B[N,K]^T ; A, B fp16, K-major, K mult of 64, rows 16B-aligned.
// EPI: 1 fp32+bias, 2 half *alpha -> Ph(ldp),
//      4 out: p = 0.5*(val - C[ix]) + 0.5*(Xh+Xl)[ip] -> hi/lo planes,
//      7 fused qkv: n0<NQK -> Ph=qkh[gm*NQK+gn]; else gv=gn-NQK: C=vf[gm*DIMN+gv] + Pl=vth transposed
template<int EPI>
__global__ void __launch_bounds__(256)
tc_gemm(const __half* __restrict__ Ah, int lda, long sA,
        const __half* __restrict__ Bh, int ldb, long sB,
        float* __restrict__ C, int ldc, long sC,
        int M, int N, int K, float alpha,
        const float* __restrict__ bias,
        const __half* __restrict__ Xh, const __half* __restrict__ Xl, long sX,
        __half* __restrict__ Ph, __half* __restrict__ Pl,
        int ldp, long sP)
{
    extern __shared__ char smem[];
    uint32_t sbase = smem_u32(smem);
    int tid = threadIdx.x, lane = tid & 31, wid = tid >> 5;
    int wm = wid >> 2, wn = wid & 3;       // warp tile 64x32 at (wm*64, wn*32)
    int z = blockIdx.z;
    Ah += (size_t)z * sA;
    Bh += (size_t)z * sB;
    if (EPI == 1 || EPI == 4 || EPI == 7) C += (size_t)z * sC;
    if (EPI == 4) { Xh += (size_t)z * sX; Xl += (size_t)z * sX; }
    if (EPI == 2 || EPI == 4) { Ph += (size_t)z * sP; if (EPI == 4) Pl += (size_t)z * sP; }
    int m0 = blockIdx.y * 128, n0 = blockIdx.x * 128;

    float acc[4][4][4];
    #pragma unroll
    for (int i = 0; i < 4; i++)
        #pragma unroll
        for (int j = 0; j < 4; j++)
            #pragma unroll
            for (int r = 0; r < 4; r++) acc[i][j][r] = 0.f;

    int arow = (lane & 7) + ((lane >> 3) & 1) * 8;
    int acol = (lane >> 4) * 8;
    int brow = (lane & 7) + ((lane >> 4) ? 8 : 0);
    int bcol = ((lane >> 3) & 1) * 8;

    auto stage_load = [&](int t) {   // t indexes k64 chunks
        uint32_t sb = sbase + (uint32_t)(t & 1) * STAGE_B;
        #pragma unroll
        for (int sub = 0; sub < 2; sub++) {
            long k0 = (long)t * 64 + sub * 32;
            uint32_t sbb = sb + (uint32_t)sub * SUB_B;
            #pragma unroll
            for (int it = 0; it < 2; it++) {
                int e = tid + it * 256;                  // 0..511
                int r = e >> 2, c4 = e & 3;
                uint32_t d = sbb + (uint32_t)(r * (SPITCH*2) + c4 * 16);
                int gm = m0 + r;
                bool okA = gm < M;
                const char* pAh = (const char*)(Ah + (long)(okA ? gm : 0) * lda + k0) + c4 * 16;
                cpasync16(d,           pAh, okA ? 16 : 0);
                int gn = n0 + r;
                bool okB = gn < N;
                const char* pBh = (const char*)(Bh + (long)(okB ? gn : 0) * ldb + k0) + c4 * 16;
                cpasync16(d + PLANE_B, pBh, okB ? 16 : 0);
            }
        }
        CP_COMMIT();
    };

    auto compute = [&](int buf) {
        uint32_t sb = sbase + (uint32_t)buf * STAGE_B;
        #pragma unroll
        for (int sub = 0; sub < 2; sub++) {
            uint32_t sbb = sb + (uint32_t)sub * SUB_B;
            uint32_t aAh = sbb +           (uint32_t)((wm*64 + arow) * (SPITCH*2) + acol*2);
            uint32_t aBh = sbb + PLANE_B + (uint32_t)((wn*32 + brow) * (SPITCH*2) + bcol*2);
            #pragma unroll
            for (int s = 0; s < 2; s++) {
                uint32_t koff = (uint32_t)(s * 16 * 2);
                uint32_t ah[4][4];
                #pragma unroll
                for (int mt = 0; mt < 4; mt++) {
                    uint32_t ro = (uint32_t)(mt * 16 * (SPITCH*2)) + koff;
                    ldsm4(ah[mt], aAh + ro);
                }
                uint32_t bh2[2][4];
                #pragma unroll
                for (int np = 0; np < 2; np++) {
                    uint32_t ro = (uint32_t)(np * 16 * (SPITCH*2)) + koff;
                    ldsm4(bh2[np], aBh + ro);
                }
                #pragma unroll
                for (int mt = 0; mt < 4; mt++)
                    #pragma unroll
                    for (int nt = 0; nt < 4; nt++)
                        mma_f16(acc[mt][nt], ah[mt], &bh2[nt >> 1][(nt & 1) * 2]);
            }
        }
    };

    int nk = K / 64;
    stage_load(0);
    for (int t = 0; t < nk; t++) {
        if (t + 1 < nk) { stage_load(t + 1); cp_wait<1>(); }
        else            { cp_wait<0>(); }
        __syncthreads();
        compute(t & 1);
        __syncthreads();
    }

    // epilogue: regs -> smem (pitch 129 floats; conflict-free rows AND columns)
    float* sst = (float*)smem;
    int g = lane >> 2, tq = lane & 3;
    #pragma unroll
    for (int mt = 0; mt < 4; mt++)
        #pragma unroll
        for (int nt = 0; nt < 4; nt++)
            #pragma unroll
            for (int r = 0; r < 4; r++) {
                int m = wm*64 + mt*16 + g + ((r >= 2) ? 8 : 0);
                int n = wn*32 + nt*8 + 2*tq + (r & 1);
                sst[m * 129 + n] = acc[mt][nt][r];
            }
    __syncthreads();

    if (EPI == 1 || EPI == 2 || EPI == 4) {
        for (int e = tid; e < 16384; e += 256) {
            int r = e >> 7, c = e & 127;
            int gm = m0 + r, gn = n0 + c;
            if (gm >= M || gn >= N) continue;
            float val = sst[r * 129 + c];
            if (EPI == 1) {
                C[(long)gm * ldc + gn] = val + bias[gn];
            } else if (EPI == 2) {
                Ph[(long)gm * ldp + gn] = __float2half(val * alpha);
            } else {  // EPI 4
                long ix = (long)gm * ldc + gn;
                long ip = (long)gm * ldp + gn;
                float xprev = __half2float(Xh[ip]) + __half2float(Xl[ip]);
                float v2 = 0.5f * (val - C[ix]) + 0.5f * xprev;
                __half h, l; bsplit(v2, h, l);
                Ph[ip] = h; Pl[ip] = l;
            }
        }
    } else {  // EPI 7: fused qkv — this block is purely qk-type or v-type (NQK % 128 == 0)
        if (n0 < NQK) {
            for (int e = tid; e < 16384; e += 256) {
                int r = e >> 7, c = e & 127;
                int gm = m0 + r, gn = n0 + c;
                if (gm >= M) continue;
                Ph[(long)gm * NQK + gn] = __float2half(sst[r * 129 + c]);
            }
        } else {
            for (int e = tid; e < 16384; e += 256) {
                int r = e >> 7, c = e & 127;
                int gm = m0 + r;
                if (gm >= M) continue;
                int gv = n0 - NQK + c;
                C[(long)gm * DIMN + gv] = sst[r * 129 + c];
            }
            for (int e = tid; e < 16384; e += 256) {
                int c = e >> 7, r = e & 127;      // consecutive tid -> consecutive r (gm)
                int gm = m0 + r;
                if (gm >= M) continue;
                int gv = n0 - NQK + c;
                float val = sst[r * 129 + c];
                int b = gm / NTOK, tok = gm - b * NTOK;
                long it = ((long)b * DIMN + gv) * NTOKP + tok;
                Pl[it] = __float2half(val);
            }
        }
    }
}

// ===================== elementwise kernels =====================
__global__ void ln1_patchify_kernel(const float* __restrict__ img,
                                    const float* __restrict__ g1,
                                    const float* __restrict__ b1) {
    int p = blockIdx.x, b = blockIdx.y, tid = threadIdx.x;
    int phh = p / 24, pw = p % 24;
    __shared__ float sv[PD];
    __shared__ float sred[256];
    int pr = tid >> 4, pc = tid & 15;
    float s1 = 0.f, s2 = 0.f;
    #pragma unroll
    for (int c = 0; c < 3; c++) {
        float v = img[(((size_t)b*3 + c)*384 + (phh*16 + pr))*384 + (pw*16 + pc)];
        sv[(pr*16 + pc)*3 + c] = v;
        s1 += v; s2 += v*v;
    }
    float tot  = block_reduce_sum(s1, sred);
    float tot2 = block_reduce_sum(s2, sred);
    float mean = tot / PD;
    float var  = tot2 / PD - mean*mean;
    float rs   = rsqrtf(var + EPSC);
    size_t base = ((size_t)b*NPATCH + p)*PD;
    for (int d = tid; d < PD; d += 256)
        g_xph[base + d] = __float2half((sv[d] - mean)*rs*g1[d] + b1[d]);
}

__global__ void ln2_assemble_kernel(const float* __restrict__ g2,
                                    const float* __restrict__ b2,
                                    const float* __restrict__ pos,
                                    const float* __restrict__ cls) {
    int t = blockIdx.x, b = blockIdx.y, tid = threadIdx.x;
    size_t base = ((size_t)b*NTOK + t)*DIMN;
    if (t == 0) {
        for (int d = tid; d < DIMN; d += 128) {
            float f = cls[d] + pos[d];
            __half h, l; bsplit(f, h, l);
            g_x0h[base + d] = h; g_x0l[base + d] = l;
        }
        return;
    }
    __shared__ float sv[DIMN];
    __shared__ float sred[128];
    const float* in = g_tmp + ((size_t)b*NPATCH + (t-1))*DIMN;
    float s1 = 0.f, s2 = 0.f;
    for (int d = tid; d < DIMN; d += 128) { float v = in[d]; sv[d] = v; s1 += v; s2 += v*v; }
    float tot  = block_reduce_sum(s1, sred);
    float tot2 = block_reduce_sum(s2, sred);
    float mean = tot / DIMN;
    float var  = tot2 / DIMN - mean*mean;
    float rs   = rsqrtf(var + EPSC);
    for (int d = tid; d < DIMN; d += 128) {
        float f = (sv[d] - mean)*rs*g2[d] + b2[d] + pos[(size_t)t*DIMN + d];
        __half h, l; bsplit(f, h, l);
        g_x0h[base + d] = h; g_x0l[base + d] = l;
    }
}

// per-layer, per-column-k stats of lv (blockIdx.y = layer)
__global__ void wvstat_kernel(const float* __restrict__ wv_raw) {
    int k = blockIdx.x, l = blockIdx.y, tid = threadIdx.x;
    const float* lv = wv_raw + (size_t)l*DIMN*DIMN;
    __shared__ float sred[128];
    float mx = -1e30f;
    for (int a = tid; a < DIMN; a += 128) mx = fmaxf(mx, lv[(size_t)a*DIMN + k]);
    sred[tid] = mx; __syncthreads();
    for (int s = 64; s > 0; s >>= 1) { if (tid < s) sred[tid] = fmaxf(sred[tid], sred[tid+s]); __syncthreads(); }
    mx = sred[0]; __syncthreads();
    float sm = 0.f;
    for (int a = tid; a < DIMN; a += 128) sm += __expf(lv[(size_t)a*DIMN + k] - mx);
    float tot = block_reduce_sum(sm, sred);
    if (tid == 0) {
        g_wvstat[(size_t)l*2*DIMN + k] = mx;
        g_wvstat[(size_t)l*2*DIMN + DIMN + k] = 1.f / (tot * (float)DIMN);
    }
}

// wv_eff^T -> rows 768..1151 of the combined per-layer weight block
__global__ void wvT_kernel(const float* __restrict__ wv_raw) {
    int n = blockIdx.x, l = blockIdx.y, tid = threadIdx.x;
    const float* lv = wv_raw + (size_t)l*DIMN*DIMN;
    const float* st = g_wvstat + (size_t)l*2*DIMN;
    size_t ob = (size_t)l*NQKV*DIMN + (size_t)(NQK + n)*DIMN;
    for (int k = tid; k < DIMN; k += 128)
        g_wqkvth[ob + k] = __float2half(__expf(lv[(size_t)n*DIMN + k] - st[k]) * st[DIMN + k]);
}

// fp32 [R,C] -> fp16 plane [C, Rpad] (zero-pad r>=R)
__global__ void transconv_kernel(const float* __restrict__ src, int R, int Cc, int pitch, long sZ,
                                 __half* __restrict__ dh, int Rpad, long dZ) {
    __shared__ float tile[32][33];
    int z = blockIdx.z;
    src += (size_t)z * sZ; dh += (size_t)z * dZ;
    int rb = blockIdx.x * 32, cb = blockIdx.y * 32;
    int tx = threadIdx.x, ty = threadIdx.y;   // 32 x 8
    #pragma unroll
    for (int i = 0; i < 4; i++) {
        int r = rb + ty + i*8, c = cb + tx;
        tile[ty + i*8][tx] = (r < R && c < Cc) ? src[(long)r*pitch + c] : 0.f;
    }
    __syncthreads();
    #pragma unroll
    for (int i = 0; i < 4; i++) {
        int dr = cb + ty + i*8;
        int dc = rb + tx;
        if (dr < Cc && dc < Rpad)
            dh[(long)dr*Rpad + dc] = __float2half(tile[tx][ty + i*8]);
    }
}

// column softmax over axis i of fp16 scores -> probs hi plane [i][NTOKP]
// block 128 = 32 cols x 4 row-groups; grid (ceil(NTOK/32), BSZ)
__global__ void colsoftmax_kernel() {
    int b = blockIdx.y;
    int tx = threadIdx.x & 31, ty = threadIdx.x >> 5;
    int j = blockIdx.x * 32 + tx;
    __shared__ float sm_[4][32], ss_[4][32];
    const __half* s = g_s + (size_t)b*NTOK*NTOK;
    float m = -1e30f, sum = 0.f;
    if (j < NTOK) {
        for (int i = ty; i < NTOK; i += 4) {
            float v = __half2float(s[(size_t)i*NTOK + j]);
            float nm = fmaxf(m, v);
            sum = sum * __expf(m - nm) + __expf(v - nm);
            m = nm;
        }
    }
    sm_[ty][tx] = m; ss_[ty][tx] = sum;
    __syncthreads();
    if (ty == 0) {
        float M = sm_[0][tx], S = ss_[0][tx];
        #pragma unroll
        for (int t2 = 1; t2 < 4; t2++) {
            float m2 = sm_[t2][tx], s2 = ss_[t2][tx];
            float nm = fmaxf(M, m2);
            S = S * __expf(M - nm) + s2 * __expf(m2 - nm);
            M = nm;
        }
        sm_[0][tx] = M; ss_[0][tx] = 1.f / S;
    }
    __syncthreads();
    if (j >= NTOK) return;
    float M = sm_[0][tx], inv = ss_[0][tx];
    __half* ph = g_ph + (size_t)b*NTOK*NTOKP;
    for (int i = ty; i < NTOK; i += 4)
        ph[(size_t)i*NTOKP + j] = __float2half(__expf(__half2float(s[(size_t)i*NTOK + j]) - M) * inv);
}

__global__ void head_kernel(const __half* __restrict__ xh,
                            const __half* __restrict__ xl,
                            const float* __restrict__ Wh,
                            const float* __restrict__ bh,
                            float* __restrict__ out) {
    int b = blockIdx.x, tid = threadIdx.x;
    __shared__ float sx[DIMN];
    for (int d = tid; d < DIMN; d += 256) {
        size_t ix = (size_t)b*NTOK*DIMN + d;
        sx[d] = __half2float(xh[ix]) + __half2float(xl[ix]);
    }
    __syncthreads();
    for (int n = tid; n < NCLS; n += 256) {
        float acc = bh[n];
        #pragma unroll 4
        for (int kk = 0; kk < DIMN; kk++)
            acc += sx[kk] * Wh[(size_t)kk*NCLS + n];
        out[(size_t)b*NCLS + n] = acc;
    }
}

// ===================== launch =====================
extern "C" void kernel_launch(void* const* d_in, const int* in_sizes, int n_in,
                              void* d_out, int out_size) {
    const float* img    = (const float*)d_in[0];
    const float* ln1_g  = (const float*)d_in[1];
    const float* ln1_b  = (const float*)d_in[2];
    const float* Wp     = (const float*)d_in[3];
    const float* bp     = (const float*)d_in[4];
    const float* ln2_g  = (const float*)d_in[5];
    const float* ln2_b  = (const float*)d_in[6];
    const float* pos    = (const float*)d_in[7];
    const float* cls    = (const float*)d_in[8];
    const float* wk     = (const float*)d_in[9];
    const float* wq     = (const float*)d_in[10];
    const float* wv_raw = (const float*)d_in[11];
    const float* Wh     = (const float*)d_in[12];
    const float* bh     = (const float*)d_in[13];
    float* out = (float*)d_out;

    cudaFuncSetAttribute(tc_gemm<1>, cudaFuncAttributeMaxDynamicSharedMemorySize, SMEM_BYTES);
    cudaFuncSetAttribute(tc_gemm<2>, cudaFuncAttributeMaxDynamicSharedMemorySize, SMEM_BYTES);
    cudaFuncSetAttribute(tc_gemm<4>, cudaFuncAttributeMaxDynamicSharedMemorySize, SMEM_BYTES);
    cudaFuncSetAttribute(tc_gemm<7>, cudaFuncAttributeMaxDynamicSharedMemorySize, SMEM_BYTES);

    float *tmp, *vf;
    cudaGetSymbolAddress((void**)&tmp, g_tmp);
    cudaGetSymbolAddress((void**)&vf,  g_vf);
    __half *sf, *xph, *wpth, *wqkvth;
    __half *x0h,*x0l,*x1h,*x1l,*qkh,*vth,*pph;
    cudaGetSymbolAddress((void**)&sf,  g_s);
    cudaGetSymbolAddress((void**)&xph, g_xph);
    cudaGetSymbolAddress((void**)&wpth, g_wpth);
    cudaGetSymbolAddress((void**)&wqkvth, g_wqkvth);
    cudaGetSymbolAddress((void**)&x0h, g_x0h);     cudaGetSymbolAddress((void**)&x0l, g_x0l);
    cudaGetSymbolAddress((void**)&x1h, g_x1h);     cudaGetSymbolAddress((void**)&x1l, g_x1l);
    cudaGetSymbolAddress((void**)&qkh, g_qkh);
    cudaGetSymbolAddress((void**)&vth, g_vth);
    cudaGetSymbolAddress((void**)&pph, g_ph);

    const float scale = 1.f / sqrtf((float)NTOK);
    const long sTok = (long)NTOK * DIMN;
    const long sSc  = (long)NTOK * NTOK;
    const long sP   = (long)NTOK * NTOKP;
    const long sVT  = (long)DIMN * NTOKP;
    const long sQK  = (long)NTOK * NQK;
    const long sWL  = (long)DIMN * DIMN;     // src stride per layer
    const long sW3  = (long)NQKV * DIMN;     // dst stride per layer (combined qkv)

    // ---- upfront preprocessing ----
    ln1_patchify_kernel<<<dim3(NPATCH, BSZ), 256>>>(img, ln1_g, ln1_b);
    transconv_kernel<<<dim3(PD/32, DIMN/32, 1), dim3(32,8)>>>(Wp, PD, DIMN, DIMN, 0, wpth, PD, 0);
    // wq^T -> rows 0..383, wk^T -> rows 384..767, wv_eff^T -> rows 768..1151 (per layer)
    transconv_kernel<<<dim3(DIMN/32, DIMN/32, DEPTH), dim3(32,8)>>>(
        wq, DIMN, DIMN, DIMN, sWL, wqkvth, DIMN, sW3);
    transconv_kernel<<<dim3(DIMN/32, DIMN/32, DEPTH), dim3(32,8)>>>(
        wk, DIMN, DIMN, DIMN, sWL, wqkvth + (size_t)DIMN*DIMN, DIMN, sW3);
    wvstat_kernel<<<dim3(DIMN, DEPTH), 128>>>(wv_raw);
    wvT_kernel<<<dim3(DIMN, DEPTH), 128>>>(wv_raw);

    // patch embed: tmp = xp @ Wp + bp  (K=768)
    tc_gemm<1><<<dim3(DIMN/128, MPAT/128, 1), 256, SMEM_BYTES>>>(
        xph, PD, 0, wpth, PD, 0, tmp, DIMN, 0,
        MPAT, DIMN, PD, 0.f, bp, nullptr, nullptr, 0, nullptr, nullptr, 0, 0);
    ln2_assemble_kernel<<<dim3(NTOK, BSZ), 128>>>(ln2_g, ln2_b, pos, cls);

    __half *curh = x0h, *curl = x0l;
    __half *nxth = x1h, *nxtl = x1l;
    const dim3 gQKV(NQKV/128, (MTOK + 127)/128, 1);          // (9,145)
    const dim3 gSC((NTOK + 127)/128, (NTOK + 127)/128, BSZ); // (5,5,32)
    const dim3 gOUT(DIMN/128, (NTOK + 127)/128, BSZ);        // (3,5,32)

    for (int l = 0; l < DEPTH; l++) {
        const __half* w3 = wqkvth + (size_t)l * sW3;

        // fused qkv = x @ [wq | wk | wv_eff]  (K=384)
        tc_gemm<7><<<gQKV, 256, SMEM_BYTES>>>(
            curh, DIMN, 0, w3, DIMN, 0, vf, DIMN, 0,
            MTOK, NQKV, DIMN, 0.f, nullptr, nullptr, nullptr, 0, qkh, vth, NQK, 0);
        // scores = scale * q @ k^T -> fp16  (K=384, batched)
        tc_gemm<2><<<gSC, 256, SMEM_BYTES>>>(
            qkh, NQK, sQK, qkh + 384, NQK, sQK, nullptr, 0, 0,
            NTOK, NTOK, DIMN, scale, nullptr, nullptr, nullptr, 0, sf, nullptr, NTOK, sSc);
        // column softmax -> probs hi plane
        colsoftmax_kernel<<<dim3((NTOK + 31)/32, BSZ), 128>>>();
        // x_new = 0.5*(probs @ v - v) + 0.5*x  -> hi/lo planes  (K=640, batched)
        tc_gemm<4><<<gOUT, 256, SMEM_BYTES>>>(
            pph, NTOKP, sP, vth, NTOKP, sVT, vf, DIMN, sTok,
            NTOK, DIMN, NTOKP, 0.f, nullptr, curh, curl, sTok, nxth, nxtl, DIMN, sTok);

        __half* th = curh; curh = nxth; nxth = th;
        __half* tl = curl; curl = nxtl; nxtl = tl;
    }
    head_kernel<<<BSZ, 256>>>(curh, curl, Wh, bh, out);
}